// round 7
// baseline (speedup 1.0000x reference)
#include <cuda_runtime.h>
#include <math.h>

#define BATCH 8192
#define NVRT  778
#define NJO   21
#define NF    135
#define NM    336      /* 21*16 */
#define NN    1008     /* NM*3  */
#define NNP   1024
#define NFC   405      /* NF*3  */
#define PPLD  784
#define KSPLIT 4
#define KSEG  196      /* PPLD / KSPLIT */

// ---------------- scratch (__device__ globals; zero-init; padding never written) ----
__device__ float g_vsh[NVRT * 3];
__device__ float g_Jk[64];
__device__ float g_W2T[NM * PPLD];       // [m][v], rows padded to 784 (tail stays 0)
__device__ float g_Pp[NFC * PPLD];       // [fc][v], tail stays 0
__device__ float g_M[NM];
__device__ float g_C0[NNP];              // [1008..1024) stays 0
__device__ float g_Dp[KSPLIT * NF * NNP];// split-K partials (padding never written -> 0)
__device__ float g_D[NF * NNP];          // combined (padding written 0 by reduce)

// ---------------- f32x2 helpers ----------------
typedef unsigned long long u64;
__device__ __forceinline__ u64 pk2(float x, float y) {
    u64 r; asm("mov.b64 %0, {%1, %2};" : "=l"(r) : "f"(x), "f"(y)); return r;
}
__device__ __forceinline__ void upk2(u64 v, float& x, float& y) {
    asm("mov.b64 {%0, %1}, %2;" : "=f"(x), "=f"(y) : "l"(v));
}
__device__ __forceinline__ u64 fma2(u64 a, u64 b, u64 c) {
    u64 d; asm("fma.rn.f32x2 %0, %1, %2, %3;" : "=l"(d) : "l"(a), "l"(b), "l"(c)); return d;
}

// ================ stage A: vsh + W2T (25 blocks)  ||  Pp transpose (1231 blocks) ========
#define PP_BLKS ((NFC * NVRT + 255) / 256)
__global__ void k_A(const float* __restrict__ us, const float* __restrict__ sd,
                    const float* __restrict__ vt, const float* __restrict__ Jr,
                    const float* __restrict__ wg, const float* __restrict__ pd) {
    int t = threadIdx.x;
    if (blockIdx.x < 25) {
        __shared__ float jrs[32 * 21];
        __shared__ float wgs[32 * 17];
        int v0 = blockIdx.x * 32;
        int nv = NVRT - v0; if (nv > 32) nv = 32;
        for (int i = t; i < nv * 21; i += 256) jrs[i] = Jr[v0 * 21 + i];
        for (int i = t; i < nv * 16; i += 256) {
            int vl = i >> 4, j = i & 15;
            wgs[vl * 17 + j] = wg[(v0 + vl) * 16 + j];
        }
        for (int i = t; i < nv * 3; i += 256) {
            int g = v0 * 3 + i;
            float s = vt[g];
#pragma unroll
            for (int q = 0; q < 10; q++) s += us[q] * sd[q * 2334 + g];
            g_vsh[g] = s;
        }
        __syncthreads();
        for (int i = t; i < NM * 32; i += 256) {
            int vl = i & 31, m = i >> 5;
            int v = v0 + vl;
            if (v < NVRT)
                g_W2T[m * PPLD + v] = jrs[vl * 21 + (m >> 4)] * wgs[vl * 17 + (m & 15)];
        }
    } else {
        int idx = (blockIdx.x - 25) * 256 + t;
        if (idx < NFC * NVRT) {
            int fc = idx / NVRT, v = idx - fc * NVRT;
            int f = fc / 3, c = fc - 3 * f;
            g_Pp[fc * PPLD + v] = pd[f * 2334 + 3 * v + c];
        }
    }
}

// ================ stage B: Jk/M/C0 (399 blocks)  ||  D split-K partials (572 blocks) ====
__global__ void k_B(const float* __restrict__ Jr) {
    int t = threadIdx.x;
    int blk = blockIdx.x;
    if (blk < NM + 63) {
        __shared__ float vs[NVRT * 3];
        __shared__ float red[4][256];
        for (int i = t; i < NVRT * 3; i += 256) vs[i] = g_vsh[i];
        __syncthreads();
        if (blk < NM) {
            int m = blk;
            float sm = 0.f, s0 = 0.f, s1 = 0.f, s2 = 0.f;
            for (int v = t; v < NVRT; v += 256) {
                float w = g_W2T[m * PPLD + v];
                sm += w;
                s0 += w * vs[v * 3 + 0];
                s1 += w * vs[v * 3 + 1];
                s2 += w * vs[v * 3 + 2];
            }
            red[0][t] = sm; red[1][t] = s0; red[2][t] = s1; red[3][t] = s2;
            __syncthreads();
            for (int o = 128; o > 0; o >>= 1) {
                if (t < o) {
                    red[0][t] += red[0][t + o]; red[1][t] += red[1][t + o];
                    red[2][t] += red[2][t + o]; red[3][t] += red[3][t + o];
                }
                __syncthreads();
            }
            if (t == 0) {
                g_M[m] = red[0][0];
                g_C0[m * 3 + 0] = red[1][0];
                g_C0[m * 3 + 1] = red[2][0];
                g_C0[m * 3 + 2] = red[3][0];
            }
        } else {
            int idx = blk - NM;
            int j = idx / 3, c = idx - 3 * j;
            float s = 0.f;
            for (int v = t; v < NVRT; v += 256) s += vs[v * 3 + c] * Jr[v * 21 + j];
            red[0][t] = s; __syncthreads();
            for (int o = 128; o > 0; o >>= 1) {
                if (t < o) red[0][t] += red[0][t + o];
                __syncthreads();
            }
            if (t == 0) g_Jk[j * 3 + c] = red[0][0];
        }
    } else {
        __shared__ float As[32][33];
        __shared__ float Bs[32][33];
        int b2 = blk - (NM + 63);
        int ks = b2 / 143;
        int rem = b2 - ks * 143;
        int m0 = (rem % 11) * 32;
        int fc0 = (rem / 11) * 32;
        int kbase = ks * KSEG, kend = kbase + KSEG;
        int tx = t & 15, ty = t >> 4;
        float acc[2][2] = {};
        for (int k0 = kbase; k0 < kend; k0 += 32) {
#pragma unroll
            for (int r = 0; r < 4; r++) {
                int e = t + 256 * r; int kk = e & 31, fl = e >> 5;
                int fc = fc0 + fl, k = k0 + kk;
                As[fl][kk] = (fc < NFC && k < kend) ? g_Pp[fc * PPLD + k] : 0.f;
            }
#pragma unroll
            for (int r = 0; r < 4; r++) {
                int e = t + 256 * r; int kk = e & 31, ml = e >> 5;
                int m = m0 + ml, k = k0 + kk;
                Bs[ml][kk] = (m < NM && k < kend) ? g_W2T[m * PPLD + k] : 0.f;
            }
            __syncthreads();
#pragma unroll
            for (int kk = 0; kk < 32; kk++) {
                float a0 = As[ty][kk], a1 = As[ty + 16][kk];
                float b0 = Bs[tx][kk], b1 = Bs[tx + 16][kk];
                acc[0][0] += a0 * b0; acc[0][1] += a0 * b1;
                acc[1][0] += a1 * b0; acc[1][1] += a1 * b1;
            }
            __syncthreads();
        }
#pragma unroll
        for (int i = 0; i < 2; i++) {
            int fc = fc0 + ty + 16 * i;
            if (fc >= NFC) continue;
            int f = fc / 3, c = fc - 3 * f;
#pragma unroll
            for (int jj = 0; jj < 2; jj++) {
                int m = m0 + tx + 16 * jj;
                if (m < NM) g_Dp[(ks * NF + f) * NNP + m * 3 + c] = acc[i][jj];
            }
        }
    }
}

// ================ stage C: combine split-K partials ================
__global__ void k_red() {
    int idx = blockIdx.x * 256 + threadIdx.x;   // grid covers NF*NNP exactly
    const int S = NF * NNP;
    g_D[idx] = (g_Dp[idx] + g_Dp[S + idx]) + (g_Dp[2 * S + idx] + g_Dp[3 * S + idx]);
}

// ================ fused: pose features + chain + GEMM + epilogue ================
// 1024 threads, 32 batches per block. f32x2 lanes = two ADJACENT n.
// Thread: tn = t & 511 -> n = {2tn, 2tn+1}; h = t >> 9 -> batches 16h..16h+15.
// smem float layout:
//   Ps  [0 .. 32256)      32 x 1008  (aliased early: ths [0..1440), pfd [1440..10080))
//   Asm [32256 .. 38400)  32 x 192
//   Ms  [38400 .. 38736)
//   Ts  [38736 .. 38832)
//   Jks [38832 .. 38880)
// pfd: [f][b] u64 with pf value DUPLICATED in both halves -> broadcast LDS gives operand.
#define SMEM_BYTES (38880 * 4)

__device__ __forceinline__ void gstep(u64 d01, unsigned sp, u64 (&a0)[16]) {
#pragma unroll
    for (int bq = 0; bq < 8; bq++) {
        u64 p0, p1;
        asm("ld.shared.v2.u64 {%0, %1}, [%2];"
            : "=l"(p0), "=l"(p1) : "r"(sp + bq * 16));
        a0[2 * bq]     = fma2(d01, p0, a0[2 * bq]);
        a0[2 * bq + 1] = fma2(d01, p1, a0[2 * bq + 1]);
    }
}

__global__ __launch_bounds__(1024, 1)
void k_fused(const float* __restrict__ theta, const float* __restrict__ dq,
             const float* __restrict__ iq, const float* __restrict__ tr,
             float* __restrict__ out) {
    extern __shared__ float sm[];
    float* Ps  = sm;
    float* Asm = sm + 32256;
    float* Ms  = sm + 38400;
    float* Ts  = sm + 38736;
    float* Jks = sm + 38832;
    float* ths = sm;                 // alias (dead before Ps writes)
    u64*  pfd  = (u64*)(sm + 1440);  // alias (dead before Ps writes); [f*32 + b]
    float* pff = sm + 1440;          // float view of pfd

    int t = threadIdx.x;
    int b0 = blockIdx.x * 32;
    int tn = t & 511, h = t >> 9;

    // ---- stage inputs ----
    for (int i = t; i < 1440; i += 1024) ths[i] = theta[b0 * 45 + i];
    if (t >= 1024 - 96 && t < 1024 - 96 + 48) { int i = t - (1024 - 96); Jks[i] = g_Jk[i]; }
    if (t >= 512 && t < 512 + NM) Ms[t - 512] = g_M[t - 512];
    if (t < 96) Ts[t] = tr[b0 * 3 + t];
    __syncthreads();

    // ---- pose features: 480 threads, one per (batch, rot); store duplicated u64 ----
    if (t < 480) {
        int bl = t / 15, i = t - bl * 15;
        const float* th = ths + bl * 45 + 3 * i;
        float tx = th[0], ty = th[1], tz = th[2];
        float ax = tx + 1e-8f, ay = ty + 1e-8f, az = tz + 1e-8f;
        float angle = sqrtf(ax * ax + ay * ay + az * az);
        float inv = 1.0f / angle;
        float nx = tx * inv, ny = ty * inv, nz = tz * inv;
        float sh, ch;
        sincosf(0.5f * angle, &sh, &ch);
        float qw = ch, qx = sh * nx, qy = sh * ny, qz = sh * nz;
        float qn = rsqrtf(qw * qw + qx * qx + qy * qy + qz * qz);
        qw *= qn; qx *= qn; qy *= qn; qz *= qn;
        float w2 = qw * qw, x2 = qx * qx, y2 = qy * qy, z2 = qz * qz;
        float wx = qw * qx, wy = qw * qy, wz = qw * qz;
        float xy = qx * qy, xz = qx * qz, yz = qy * qz;
        float o[9];
        o[0] = w2 + x2 - y2 - z2 - 1.0f;
        o[1] = 2.f * (xy - wz);
        o[2] = 2.f * (wy + xz);
        o[3] = 2.f * (wz + xy);
        o[4] = w2 - x2 + y2 - z2 - 1.0f;
        o[5] = 2.f * (yz - wx);
        o[6] = 2.f * (xz - wy);
        o[7] = 2.f * (wx + yz);
        o[8] = w2 - x2 - y2 + z2 - 1.0f;
#pragma unroll
        for (int e = 0; e < 9; e++)
            pfd[(9 * i + e) * 32 + bl] = pk2(o[e], o[e]);
    }
    __syncthreads();

    // ---- kinematic chain: 96 threads, one per (batch, row k) ----
    if (t < 96) {
        int bl = t / 3, k = t - bl * 3;
        int b = b0 + bl;
        float w1 = dq[b * 4 + 0], x1 = dq[b * 4 + 1], y1 = dq[b * 4 + 2], z1 = dq[b * 4 + 3];
        float w2q = iq[0], x2q = iq[1], y2q = iq[2], z2q = iq[3];
        float qw = w1 * w2q - x1 * x2q - y1 * y2q - z1 * z2q;
        float qx = w1 * x2q + x1 * w2q + y1 * z2q - z1 * y2q;
        float qy = w1 * y2q - x1 * z2q + y1 * w2q + z1 * x2q;
        float qz = w1 * z2q + x1 * y2q - y1 * x2q + z1 * w2q;
        float qn = rsqrtf(qw * qw + qx * qx + qy * qy + qz * qz);
        qw *= qn; qx *= qn; qy *= qn; qz *= qn;
        float W2_ = qw * qw, X2 = qx * qx, Y2 = qy * qy, Z2 = qz * qz;
        float WX = qw * qx, WY = qw * qy, WZ = qw * qz;
        float XY = qx * qy, XZ = qx * qz, YZ = qy * qz;
        float R[9];
        R[0] = W2_ + X2 - Y2 - Z2; R[1] = 2.f * (XY - WZ);    R[2] = 2.f * (WY + XZ);
        R[3] = 2.f * (WZ + XY);    R[4] = W2_ - X2 + Y2 - Z2; R[5] = 2.f * (YZ - WX);
        R[6] = 2.f * (XZ - WY);    R[7] = 2.f * (WX + YZ);    R[8] = W2_ - X2 - Y2 + Z2;

        float rr0 = R[3 * k + 0], rr1 = R[3 * k + 1], rr2 = R[3 * k + 2];
        float rt = Jks[k];
        float* Ao = Asm + bl * 192;
        {
            float jx = Jks[0], jy = Jks[1], jz = Jks[2];
            Ao[k * 3 + 0] = rr0; Ao[k * 3 + 1] = rr1; Ao[k * 3 + 2] = rr2;
            Ao[9 + k] = rt - (rr0 * jx + rr1 * jy + rr2 * jz);
        }
#pragma unroll
        for (int chn = 0; chn < 5; chn++) {
            float cr0 = rr0, cr1 = rr1, cr2 = rr2, ct = rt;
#pragma unroll
            for (int s = 0; s < 3; s++) {
                int i = chn * 3 + 1 + s;
                int p = (s == 0) ? 0 : (i - 1);
                float Ri[9];
#pragma unroll
                for (int e = 0; e < 9; e++)
                    Ri[e] = pff[((9 * (i - 1) + e) * 32 + bl) * 2]
                          + ((e == 0 || e == 4 || e == 8) ? 1.0f : 0.0f);
                float rx = Jks[3 * i + 0] - Jks[3 * p + 0];
                float ry = Jks[3 * i + 1] - Jks[3 * p + 1];
                float rz = Jks[3 * i + 2] - Jks[3 * p + 2];
                float n0 = cr0 * Ri[0] + cr1 * Ri[3] + cr2 * Ri[6];
                float n1 = cr0 * Ri[1] + cr1 * Ri[4] + cr2 * Ri[7];
                float n2 = cr0 * Ri[2] + cr1 * Ri[5] + cr2 * Ri[8];
                float nt = cr0 * rx + cr1 * ry + cr2 * rz + ct;
                float jx = Jks[3 * i + 0], jy = Jks[3 * i + 1], jz = Jks[3 * i + 2];
                float* Aoi = Ao + i * 12;
                Aoi[k * 3 + 0] = n0; Aoi[k * 3 + 1] = n1; Aoi[k * 3 + 2] = n2;
                Aoi[9 + k] = nt - (n0 * jx + n1 * jy + n2 * jz);
                cr0 = n0; cr1 = n1; cr2 = n2; ct = nt;
            }
        }
    }

    // ---- main GEMM: n = {2tn, 2tn+1}, batches 16h..16h+15, depth-4 prefetch ----
    u64 a0[16];
    {
        u64 cc = *(const u64*)&g_C0[2 * tn];
#pragma unroll
        for (int b = 0; b < 16; b++) a0[b] = cc;
    }
    const u64* dl = (const u64*)(g_D + 2 * tn);   // row r at dl[r*512]
    u64 dbuf[4];
    dbuf[0] = dl[0]; dbuf[1] = dl[512]; dbuf[2] = dl[1024]; dbuf[3] = dl[1536];
    dl += 4 * 512;                                // points at row 4

    unsigned sp;
    {
        unsigned pbase = (unsigned)__cvta_generic_to_shared(pfd);
        sp = pbase + h * 128;                     // per-f stride 256 B
    }

    for (int f0 = 0; f0 < 128; f0 += 4) {
#pragma unroll
        for (int u = 0; u < 4; u++) {
            u64 dc = dbuf[u];
            dbuf[u] = dl[u * 512];                // row f0+u+4 (<= 131, always valid)
            gstep(dc, sp + u * 256, a0);
        }
        dl += 2048;
        sp += 1024;
    }
    // dbuf holds rows 128..131; dl points at row 132
#pragma unroll
    for (int u = 0; u < 3; u++) {
        u64 dc = dbuf[u];
        dbuf[u] = dl[u * 512];                    // rows 132..134
        gstep(dc, sp + u * 256, a0);              // f = 128..130
    }
    gstep(dbuf[3], sp + 3 * 256, a0);             // f = 131
#pragma unroll
    for (int u = 0; u < 3; u++) {
        gstep(dbuf[u], sp + (4 + u) * 256, a0);   // f = 132..134
    }
    __syncthreads();   // pfd/ths now dead

    // ---- spill P to smem ----
    if (tn < 504) {
#pragma unroll
        for (int b = 0; b < 16; b++) {
            int bg = 16 * h + b;
            float x0, x1;
            upk2(a0[b], x0, x1);
            *(float2*)&Ps[bg * NN + 2 * tn] = make_float2(x0, x1);
        }
    }
    __syncthreads();

    // ---- epilogue: joints = A ∘ P + M*t + trans ----
    for (int idx = t; idx < 32 * 63; idx += 1024) {
        int bl = idx / 63;
        int r = idx - bl * 63;
        int jo = r / 3;
        int k = r - jo * 3;
        const float* Ab = Asm + bl * 192;
        const float* Pb = Ps + bl * NN;
        float s = Ts[bl * 3 + k];
#pragma unroll
        for (int j = 0; j < 16; j++) {
            int rb = j * 12 + k * 3;
            int pb = (jo * 16 + j) * 3;
            s += Ab[rb] * Pb[pb] + Ab[rb + 1] * Pb[pb + 1] + Ab[rb + 2] * Pb[pb + 2]
               + Ms[jo * 16 + j] * Ab[j * 12 + 9 + k];
        }
        out[(b0 + bl) * 63 + jo * 3 + k] = s;
    }
}

// ---------------- launcher ----------------
extern "C" void kernel_launch(void* const* d_in, const int* in_sizes, int n_in,
                              void* d_out, int out_size) {
    const float* theta = (const float*)d_in[0];
    const float* dq    = (const float*)d_in[1];
    const float* us    = (const float*)d_in[2];
    const float* iq    = (const float*)d_in[3];
    const float* tr    = (const float*)d_in[4];
    const float* vt    = (const float*)d_in[5];
    const float* sd    = (const float*)d_in[6];
    const float* Jr    = (const float*)d_in[7];
    const float* pd    = (const float*)d_in[8];
    const float* wg    = (const float*)d_in[9];
    float* out = (float*)d_out;

    cudaFuncSetAttribute(k_fused, cudaFuncAttributeMaxDynamicSharedMemorySize, SMEM_BYTES);

    k_A<<<25 + PP_BLKS, 256>>>(us, sd, vt, Jr, wg, pd);
    k_B<<<NM + 63 + 143 * KSPLIT, 256>>>(Jr);
    k_red<<<(NF * NNP) / 256, 256>>>();
    k_fused<<<BATCH / 32, 1024, SMEM_BYTES>>>(theta, dq, iq, tr, out);
}

// round 8
// speedup vs baseline: 1.5023x; 1.5023x over previous
#include <cuda_runtime.h>
#include <math.h>

#define BATCH 8192
#define NVRT  778
#define NJO   21
#define NF    135
#define NM    336      /* 21*16 */
#define NN    1008     /* NM*3  */
#define NNP   1024
#define NFC   405      /* NF*3  */
#define PPLD  784
#define KSPLIT 8
#define KSEG  98       /* PPLD / KSPLIT */

// ---------------- scratch (__device__ globals; zero-init; padding never written) ----
__device__ float g_vsh[NVRT * 3];
__device__ float g_Jk[64];
__device__ float g_W2T[NM * PPLD];       // [m][v], rows padded to 784 (tail stays 0)
__device__ float g_Pp[NFC * PPLD];       // [fc][v], tail stays 0
__device__ float g_M[NM];
__device__ float g_C0[NNP];              // [1008..1024) stays 0
__device__ float g_Dp[KSPLIT * NF * NNP];// split-K partials (padding never written -> 0)
__device__ float g_D[NF * NNP];          // combined (padding written 0 by reduce)

// ---------------- f32x2 helpers ----------------
typedef unsigned long long u64;
__device__ __forceinline__ u64 pk2(float x, float y) {
    u64 r; asm("mov.b64 %0, {%1, %2};" : "=l"(r) : "f"(x), "f"(y)); return r;
}
__device__ __forceinline__ void upk2(u64 v, float& x, float& y) {
    asm("mov.b64 {%0, %1}, %2;" : "=f"(x), "=f"(y) : "l"(v));
}
__device__ __forceinline__ u64 fma2(u64 a, u64 b, u64 c) {
    u64 d; asm("fma.rn.f32x2 %0, %1, %2, %3;" : "=l"(d) : "l"(a), "l"(b), "l"(c)); return d;
}

// ================ stage A: vsh + W2T (25 blocks)  ||  Pp transpose (1231 blocks) ========
#define PP_BLKS ((NFC * NVRT + 255) / 256)
__global__ void k_A(const float* __restrict__ us, const float* __restrict__ sd,
                    const float* __restrict__ vt, const float* __restrict__ Jr,
                    const float* __restrict__ wg, const float* __restrict__ pd) {
    int t = threadIdx.x;
    if (blockIdx.x < 25) {
        __shared__ float jrs[32 * 21];
        __shared__ float wgs[32 * 17];
        int v0 = blockIdx.x * 32;
        int nv = NVRT - v0; if (nv > 32) nv = 32;
        for (int i = t; i < nv * 21; i += 256) jrs[i] = Jr[v0 * 21 + i];
        for (int i = t; i < nv * 16; i += 256) {
            int vl = i >> 4, j = i & 15;
            wgs[vl * 17 + j] = wg[(v0 + vl) * 16 + j];
        }
        for (int i = t; i < nv * 3; i += 256) {
            int g = v0 * 3 + i;
            float s = vt[g];
#pragma unroll
            for (int q = 0; q < 10; q++) s += us[q] * sd[q * 2334 + g];
            g_vsh[g] = s;
        }
        __syncthreads();
        for (int i = t; i < NM * 32; i += 256) {
            int vl = i & 31, m = i >> 5;
            int v = v0 + vl;
            if (v < NVRT)
                g_W2T[m * PPLD + v] = jrs[vl * 21 + (m >> 4)] * wgs[vl * 17 + (m & 15)];
        }
    } else {
        int idx = (blockIdx.x - 25) * 256 + t;
        if (idx < NFC * NVRT) {
            int fc = idx / NVRT, v = idx - fc * NVRT;
            int f = fc / 3, c = fc - 3 * f;
            g_Pp[fc * PPLD + v] = pd[f * 2334 + 3 * v + c];
        }
    }
}

// ================ stage B: Jk/M/C0 (399 blocks)  ||  D split-K partials ====
__global__ void k_B(const float* __restrict__ Jr) {
    int t = threadIdx.x;
    int blk = blockIdx.x;
    if (blk < NM + 63) {
        __shared__ float vs[NVRT * 3];
        __shared__ float red[4][256];
        for (int i = t; i < NVRT * 3; i += 256) vs[i] = g_vsh[i];
        __syncthreads();
        if (blk < NM) {
            int m = blk;
            float sm = 0.f, s0 = 0.f, s1 = 0.f, s2 = 0.f;
            for (int v = t; v < NVRT; v += 256) {
                float w = g_W2T[m * PPLD + v];
                sm += w;
                s0 += w * vs[v * 3 + 0];
                s1 += w * vs[v * 3 + 1];
                s2 += w * vs[v * 3 + 2];
            }
            red[0][t] = sm; red[1][t] = s0; red[2][t] = s1; red[3][t] = s2;
            __syncthreads();
            for (int o = 128; o > 0; o >>= 1) {
                if (t < o) {
                    red[0][t] += red[0][t + o]; red[1][t] += red[1][t + o];
                    red[2][t] += red[2][t + o]; red[3][t] += red[3][t + o];
                }
                __syncthreads();
            }
            if (t == 0) {
                g_M[m] = red[0][0];
                g_C0[m * 3 + 0] = red[1][0];
                g_C0[m * 3 + 1] = red[2][0];
                g_C0[m * 3 + 2] = red[3][0];
            }
        } else {
            int idx = blk - NM;
            int j = idx / 3, c = idx - 3 * j;
            float s = 0.f;
            for (int v = t; v < NVRT; v += 256) s += vs[v * 3 + c] * Jr[v * 21 + j];
            red[0][t] = s; __syncthreads();
            for (int o = 128; o > 0; o >>= 1) {
                if (t < o) red[0][t] += red[0][t + o];
                __syncthreads();
            }
            if (t == 0) g_Jk[j * 3 + c] = red[0][0];
        }
    } else {
        __shared__ float As[32][33];
        __shared__ float Bs[32][33];
        int b2 = blk - (NM + 63);
        int ks = b2 / 143;
        int rem = b2 - ks * 143;
        int m0 = (rem % 11) * 32;
        int fc0 = (rem / 11) * 32;
        int kbase = ks * KSEG, kend = kbase + KSEG;
        int tx = t & 15, ty = t >> 4;
        float acc[2][2] = {};
        for (int k0 = kbase; k0 < kend; k0 += 32) {
#pragma unroll
            for (int r = 0; r < 4; r++) {
                int e = t + 256 * r; int kk = e & 31, fl = e >> 5;
                int fc = fc0 + fl, k = k0 + kk;
                As[fl][kk] = (fc < NFC && k < kend) ? g_Pp[fc * PPLD + k] : 0.f;
            }
#pragma unroll
            for (int r = 0; r < 4; r++) {
                int e = t + 256 * r; int kk = e & 31, ml = e >> 5;
                int m = m0 + ml, k = k0 + kk;
                Bs[ml][kk] = (m < NM && k < kend) ? g_W2T[m * PPLD + k] : 0.f;
            }
            __syncthreads();
#pragma unroll
            for (int kk = 0; kk < 32; kk++) {
                float a0 = As[ty][kk], a1 = As[ty + 16][kk];
                float b0 = Bs[tx][kk], b1 = Bs[tx + 16][kk];
                acc[0][0] += a0 * b0; acc[0][1] += a0 * b1;
                acc[1][0] += a1 * b0; acc[1][1] += a1 * b1;
            }
            __syncthreads();
        }
#pragma unroll
        for (int i = 0; i < 2; i++) {
            int fc = fc0 + ty + 16 * i;
            if (fc >= NFC) continue;
            int f = fc / 3, c = fc - 3 * f;
#pragma unroll
            for (int jj = 0; jj < 2; jj++) {
                int m = m0 + tx + 16 * jj;
                if (m < NM) g_Dp[(ks * NF + f) * NNP + m * 3 + c] = acc[i][jj];
            }
        }
    }
}

// ================ stage C: combine split-K partials ================
__global__ void k_red() {
    int idx = blockIdx.x * 256 + threadIdx.x;   // grid covers NF*NNP exactly
    const int S = NF * NNP;
    float s = 0.f;
#pragma unroll
    for (int k = 0; k < KSPLIT; k++) s += g_Dp[k * S + idx];
    g_D[idx] = s;
}

// ================ fused: pose features + chain + GEMM + epilogue ================
// 512 threads, 32 batches per block. f32x2 lane = TWO BATCHES (natural pf pairs).
// Thread: tn = t & 255 (active < 252) -> n = 4*tn..4*tn+3; h = t >> 8 -> pairs 8h..8h+7.
// smem float layout:
//   Ps  [0 .. 32256)      32 x 1008  (aliased early: ths [0..1440), pfp [1440..5760))
//   Asm [32256 .. 38400)  32 x 192
//   Ms  [38400 .. 38736)
//   Ts  [38736 .. 38832)
//   Jks [38832 .. 38880)
// pfp: [f][16 pairs] u64, pair p = batches (2p, 2p+1) packed.
#define SMEM_BYTES (38880 * 4)

__device__ __forceinline__ void gstep(const float4& dc, unsigned sp, u64 (&acc)[4][8]) {
    u64 d0 = pk2(dc.x, dc.x), d1 = pk2(dc.y, dc.y),
        d2 = pk2(dc.z, dc.z), d3 = pk2(dc.w, dc.w);
#pragma unroll
    for (int q = 0; q < 4; q++) {
        u64 p0, p1;
        asm("ld.shared.v2.u64 {%0, %1}, [%2];"
            : "=l"(p0), "=l"(p1) : "r"(sp + q * 16));
        acc[0][2 * q]     = fma2(d0, p0, acc[0][2 * q]);
        acc[1][2 * q]     = fma2(d1, p0, acc[1][2 * q]);
        acc[2][2 * q]     = fma2(d2, p0, acc[2][2 * q]);
        acc[3][2 * q]     = fma2(d3, p0, acc[3][2 * q]);
        acc[0][2 * q + 1] = fma2(d0, p1, acc[0][2 * q + 1]);
        acc[1][2 * q + 1] = fma2(d1, p1, acc[1][2 * q + 1]);
        acc[2][2 * q + 1] = fma2(d2, p1, acc[2][2 * q + 1]);
        acc[3][2 * q + 1] = fma2(d3, p1, acc[3][2 * q + 1]);
    }
}

__global__ __launch_bounds__(512, 1)
void k_fused(const float* __restrict__ theta, const float* __restrict__ dq,
             const float* __restrict__ iq, const float* __restrict__ tr,
             float* __restrict__ out) {
    extern __shared__ float sm[];
    float* Ps  = sm;
    float* Asm = sm + 32256;
    float* Ms  = sm + 38400;
    float* Ts  = sm + 38736;
    float* Jks = sm + 38832;
    float* ths = sm;                 // alias (dead before Ps writes)
    u64*  pfp  = (u64*)(sm + 1440);  // alias (dead before Ps writes); [f*16 + pair]
    float* pff = sm + 1440;          // float view of pfp

    int t = threadIdx.x;
    int b0 = blockIdx.x * 32;
    int tn = t & 255, h = t >> 8;

    // ---- stage inputs ----
    for (int i = t; i < 1440; i += 512) ths[i] = theta[b0 * 45 + i];
    if (t >= 416 && t < 464) { int i = t - 416; Jks[i] = g_Jk[i]; }
    for (int i = t; i < NM; i += 512) Ms[i] = g_M[i];
    if (t < 96) Ts[t] = tr[b0 * 3 + t];
    __syncthreads();

    // ---- pose features: 480 threads, one per (batch, rot); store into pair layout ----
    if (t < 480) {
        int bl = t / 15, i = t - bl * 15;
        const float* th = ths + bl * 45 + 3 * i;
        float tx = th[0], ty = th[1], tz = th[2];
        float ax = tx + 1e-8f, ay = ty + 1e-8f, az = tz + 1e-8f;
        float angle = sqrtf(ax * ax + ay * ay + az * az);
        float inv = 1.0f / angle;
        float nx = tx * inv, ny = ty * inv, nz = tz * inv;
        float sh, ch;
        sincosf(0.5f * angle, &sh, &ch);
        float qw = ch, qx = sh * nx, qy = sh * ny, qz = sh * nz;
        float qn = rsqrtf(qw * qw + qx * qx + qy * qy + qz * qz);
        qw *= qn; qx *= qn; qy *= qn; qz *= qn;
        float w2 = qw * qw, x2 = qx * qx, y2 = qy * qy, z2 = qz * qz;
        float wx = qw * qx, wy = qw * qy, wz = qw * qz;
        float xy = qx * qy, xz = qx * qz, yz = qy * qz;
        float o[9];
        o[0] = w2 + x2 - y2 - z2 - 1.0f;
        o[1] = 2.f * (xy - wz);
        o[2] = 2.f * (wy + xz);
        o[3] = 2.f * (wz + xy);
        o[4] = w2 - x2 + y2 - z2 - 1.0f;
        o[5] = 2.f * (yz - wx);
        o[6] = 2.f * (xz - wy);
        o[7] = 2.f * (wx + yz);
        o[8] = w2 - x2 - y2 + z2 - 1.0f;
        int pr = bl >> 1, lo = bl & 1;
#pragma unroll
        for (int e = 0; e < 9; e++)
            pff[((9 * i + e) * 16 + pr) * 2 + lo] = o[e];
    }
    __syncthreads();

    // ---- kinematic chain: 96 threads, one per (batch, row k) ----
    if (t < 96) {
        int bl = t / 3, k = t - bl * 3;
        int b = b0 + bl;
        float w1 = dq[b * 4 + 0], x1 = dq[b * 4 + 1], y1 = dq[b * 4 + 2], z1 = dq[b * 4 + 3];
        float w2q = iq[0], x2q = iq[1], y2q = iq[2], z2q = iq[3];
        float qw = w1 * w2q - x1 * x2q - y1 * y2q - z1 * z2q;
        float qx = w1 * x2q + x1 * w2q + y1 * z2q - z1 * y2q;
        float qy = w1 * y2q - x1 * z2q + y1 * w2q + z1 * x2q;
        float qz = w1 * z2q + x1 * y2q - y1 * x2q + z1 * w2q;
        float qn = rsqrtf(qw * qw + qx * qx + qy * qy + qz * qz);
        qw *= qn; qx *= qn; qy *= qn; qz *= qn;
        float W2_ = qw * qw, X2 = qx * qx, Y2 = qy * qy, Z2 = qz * qz;
        float WX = qw * qx, WY = qw * qy, WZ = qw * qz;
        float XY = qx * qy, XZ = qx * qz, YZ = qy * qz;
        float R[9];
        R[0] = W2_ + X2 - Y2 - Z2; R[1] = 2.f * (XY - WZ);    R[2] = 2.f * (WY + XZ);
        R[3] = 2.f * (WZ + XY);    R[4] = W2_ - X2 + Y2 - Z2; R[5] = 2.f * (YZ - WX);
        R[6] = 2.f * (XZ - WY);    R[7] = 2.f * (WX + YZ);    R[8] = W2_ - X2 - Y2 + Z2;

        float rr0 = R[3 * k + 0], rr1 = R[3 * k + 1], rr2 = R[3 * k + 2];
        float rt = Jks[k];
        float* Ao = Asm + bl * 192;
        {
            float jx = Jks[0], jy = Jks[1], jz = Jks[2];
            Ao[k * 3 + 0] = rr0; Ao[k * 3 + 1] = rr1; Ao[k * 3 + 2] = rr2;
            Ao[9 + k] = rt - (rr0 * jx + rr1 * jy + rr2 * jz);
        }
        int pr = bl >> 1, lo = bl & 1;
#pragma unroll
        for (int chn = 0; chn < 5; chn++) {
            float cr0 = rr0, cr1 = rr1, cr2 = rr2, ct = rt;
#pragma unroll
            for (int s = 0; s < 3; s++) {
                int i = chn * 3 + 1 + s;
                int p = (s == 0) ? 0 : (i - 1);
                float Ri[9];
#pragma unroll
                for (int e = 0; e < 9; e++)
                    Ri[e] = pff[((9 * (i - 1) + e) * 16 + pr) * 2 + lo]
                          + ((e == 0 || e == 4 || e == 8) ? 1.0f : 0.0f);
                float rx = Jks[3 * i + 0] - Jks[3 * p + 0];
                float ry = Jks[3 * i + 1] - Jks[3 * p + 1];
                float rz = Jks[3 * i + 2] - Jks[3 * p + 2];
                float n0 = cr0 * Ri[0] + cr1 * Ri[3] + cr2 * Ri[6];
                float n1 = cr0 * Ri[1] + cr1 * Ri[4] + cr2 * Ri[7];
                float n2 = cr0 * Ri[2] + cr1 * Ri[5] + cr2 * Ri[8];
                float nt = cr0 * rx + cr1 * ry + cr2 * rz + ct;
                float jx = Jks[3 * i + 0], jy = Jks[3 * i + 1], jz = Jks[3 * i + 2];
                float* Aoi = Ao + i * 12;
                Aoi[k * 3 + 0] = n0; Aoi[k * 3 + 1] = n1; Aoi[k * 3 + 2] = n2;
                Aoi[9 + k] = nt - (n0 * jx + n1 * jy + n2 * jz);
                cr0 = n0; cr1 = n1; cr2 = n2; ct = nt;
            }
        }
    }

    // ---- main GEMM: n = 4tn..4tn+3, pairs 8h..8h+7, depth-4 D prefetch ----
    u64 acc[4][8];
    {
        float4 cc = *(const float4*)&g_C0[4 * tn];
        u64 c0 = pk2(cc.x, cc.x), c1 = pk2(cc.y, cc.y),
            c2 = pk2(cc.z, cc.z), c3 = pk2(cc.w, cc.w);
#pragma unroll
        for (int p = 0; p < 8; p++) {
            acc[0][p] = c0; acc[1][p] = c1; acc[2][p] = c2; acc[3][p] = c3;
        }
    }
    const float4* dl = (const float4*)(g_D + 4 * tn);   // row r at dl[r*256]
    float4 dbuf[4];
    dbuf[0] = dl[0]; dbuf[1] = dl[256]; dbuf[2] = dl[512]; dbuf[3] = dl[768];
    dl += 1024;                                          // points at row 4

    unsigned sp;
    {
        unsigned pbase = (unsigned)__cvta_generic_to_shared(pfp);
        sp = pbase + h * 64;                             // per-f stride 128 B
    }

    for (int f0 = 0; f0 < 128; f0 += 4) {
#pragma unroll
        for (int u = 0; u < 4; u++) {
            float4 dc = dbuf[u];
            dbuf[u] = dl[u * 256];                       // row f0+u+4 (<= 131, valid)
            gstep(dc, sp + u * 128, acc);
        }
        dl += 1024;
        sp += 512;
    }
    // dbuf holds rows 128..131; dl points at row 132
#pragma unroll
    for (int u = 0; u < 3; u++) {
        float4 dc = dbuf[u];
        dbuf[u] = dl[u * 256];                           // rows 132..134
        gstep(dc, sp + u * 128, acc);                    // f = 128..130
    }
    gstep(dbuf[3], sp + 3 * 128, acc);                   // f = 131
#pragma unroll
    for (int u = 0; u < 3; u++) {
        gstep(dbuf[u], sp + (4 + u) * 128, acc);         // f = 132..134
    }
    __syncthreads();   // pfp/ths now dead

    // ---- spill P to smem ----
    if (tn < 252) {
#pragma unroll
        for (int p = 0; p < 8; p++) {
            int bg = 16 * h + 2 * p;
#pragma unroll
            for (int k = 0; k < 4; k++) {
                float x0, x1;
                upk2(acc[k][p], x0, x1);
                Ps[bg * NN + 4 * tn + k] = x0;
                Ps[(bg + 1) * NN + 4 * tn + k] = x1;
            }
        }
    }
    __syncthreads();

    // ---- epilogue: joints = A ∘ P + M*t + trans ----
    for (int idx = t; idx < 32 * 63; idx += 512) {
        int bl = idx / 63;
        int r = idx - bl * 63;
        int jo = r / 3;
        int k = r - jo * 3;
        const float* Ab = Asm + bl * 192;
        const float* Pb = Ps + bl * NN;
        float s = Ts[bl * 3 + k];
#pragma unroll
        for (int j = 0; j < 16; j++) {
            int rb = j * 12 + k * 3;
            int pb = (jo * 16 + j) * 3;
            s += Ab[rb] * Pb[pb] + Ab[rb + 1] * Pb[pb + 1] + Ab[rb + 2] * Pb[pb + 2]
               + Ms[jo * 16 + j] * Ab[j * 12 + 9 + k];
        }
        out[(b0 + bl) * 63 + jo * 3 + k] = s;
    }
}

// ---------------- launcher ----------------
extern "C" void kernel_launch(void* const* d_in, const int* in_sizes, int n_in,
                              void* d_out, int out_size) {
    const float* theta = (const float*)d_in[0];
    const float* dq    = (const float*)d_in[1];
    const float* us    = (const float*)d_in[2];
    const float* iq    = (const float*)d_in[3];
    const float* tr    = (const float*)d_in[4];
    const float* vt    = (const float*)d_in[5];
    const float* sd    = (const float*)d_in[6];
    const float* Jr    = (const float*)d_in[7];
    const float* pd    = (const float*)d_in[8];
    const float* wg    = (const float*)d_in[9];
    float* out = (float*)d_out;

    cudaFuncSetAttribute(k_fused, cudaFuncAttributeMaxDynamicSharedMemorySize, SMEM_BYTES);

    k_A<<<25 + PP_BLKS, 256>>>(us, sd, vt, Jr, wg, pd);
    k_B<<<NM + 63 + 143 * KSPLIT, 256>>>(Jr);
    k_red<<<(NF * NNP) / 256, 256>>>();
    k_fused<<<BATCH / 32, 512, SMEM_BYTES>>>(theta, dq, iq, tr, out);
}

// round 9
// speedup vs baseline: 1.6300x; 1.0850x over previous
#include <cuda_runtime.h>
#include <math.h>

#define BATCH 8192
#define NVRT  778
#define NJO   21
#define NF    135
#define NM    336      /* 21*16 */
#define NN    1008     /* NM*3  */
#define NNP   1024
#define NFC   405      /* NF*3  */
#define PPLD  784
#define KSPLIT 8
#define KSEG  98       /* PPLD / KSPLIT */

#define BT    28       /* batches per fused tile */
#define NTILE 293      /* ceil(8192/28) */

// ---------------- scratch (__device__ globals; zero-init; padding never written) ----
__device__ float g_vsh[NVRT * 3];
__device__ float g_Jk[64];
__device__ float g_W2T[NM * PPLD];       // [m][v], rows padded to 784 (tail stays 0)
__device__ float g_Pp[NFC * PPLD];       // [fc][v], tail stays 0
__device__ float g_M[NM];
__device__ float g_C0[NNP];              // [1008..1024) stays 0
__device__ float g_Dp[KSPLIT * NF * NNP];// split-K partials (padding never written -> 0)
__device__ float g_D[NF * NNP];          // combined (padding written 0 by reduce)

// ---------------- f32x2 helpers ----------------
typedef unsigned long long u64;
__device__ __forceinline__ u64 pk2(float x, float y) {
    u64 r; asm("mov.b64 %0, {%1, %2};" : "=l"(r) : "f"(x), "f"(y)); return r;
}
__device__ __forceinline__ void upk2(u64 v, float& x, float& y) {
    asm("mov.b64 {%0, %1}, %2;" : "=f"(x), "=f"(y) : "l"(v));
}
__device__ __forceinline__ u64 fma2(u64 a, u64 b, u64 c) {
    u64 d; asm("fma.rn.f32x2 %0, %1, %2, %3;" : "=l"(d) : "l"(a), "l"(b), "l"(c)); return d;
}

// ================ stage A: vsh + W2T (25 blocks)  ||  Pp transpose (1231 blocks) ========
#define PP_BLKS ((NFC * NVRT + 255) / 256)
__global__ void k_A(const float* __restrict__ us, const float* __restrict__ sd,
                    const float* __restrict__ vt, const float* __restrict__ Jr,
                    const float* __restrict__ wg, const float* __restrict__ pd) {
    int t = threadIdx.x;
    if (blockIdx.x < 25) {
        __shared__ float jrs[32 * 21];
        __shared__ float wgs[32 * 17];
        int v0 = blockIdx.x * 32;
        int nv = NVRT - v0; if (nv > 32) nv = 32;
        for (int i = t; i < nv * 21; i += 256) jrs[i] = Jr[v0 * 21 + i];
        for (int i = t; i < nv * 16; i += 256) {
            int vl = i >> 4, j = i & 15;
            wgs[vl * 17 + j] = wg[(v0 + vl) * 16 + j];
        }
        for (int i = t; i < nv * 3; i += 256) {
            int g = v0 * 3 + i;
            float s = vt[g];
#pragma unroll
            for (int q = 0; q < 10; q++) s += us[q] * sd[q * 2334 + g];
            g_vsh[g] = s;
        }
        __syncthreads();
        for (int i = t; i < NM * 32; i += 256) {
            int vl = i & 31, m = i >> 5;
            int v = v0 + vl;
            if (v < NVRT)
                g_W2T[m * PPLD + v] = jrs[vl * 21 + (m >> 4)] * wgs[vl * 17 + (m & 15)];
        }
    } else {
        int idx = (blockIdx.x - 25) * 256 + t;
        if (idx < NFC * NVRT) {
            int fc = idx / NVRT, v = idx - fc * NVRT;
            int f = fc / 3, c = fc - 3 * f;
            g_Pp[fc * PPLD + v] = pd[f * 2334 + 3 * v + c];
        }
    }
}

// ================ stage B: Jk/M/C0 (399 blocks)  ||  D split-K partials ====
__global__ void k_B(const float* __restrict__ Jr) {
    int t = threadIdx.x;
    int blk = blockIdx.x;
    if (blk < NM + 63) {
        __shared__ float vs[NVRT * 3];
        __shared__ float red[4][256];
        for (int i = t; i < NVRT * 3; i += 256) vs[i] = g_vsh[i];
        __syncthreads();
        if (blk < NM) {
            int m = blk;
            float sm = 0.f, s0 = 0.f, s1 = 0.f, s2 = 0.f;
            for (int v = t; v < NVRT; v += 256) {
                float w = g_W2T[m * PPLD + v];
                sm += w;
                s0 += w * vs[v * 3 + 0];
                s1 += w * vs[v * 3 + 1];
                s2 += w * vs[v * 3 + 2];
            }
            red[0][t] = sm; red[1][t] = s0; red[2][t] = s1; red[3][t] = s2;
            __syncthreads();
            for (int o = 128; o > 0; o >>= 1) {
                if (t < o) {
                    red[0][t] += red[0][t + o]; red[1][t] += red[1][t + o];
                    red[2][t] += red[2][t + o]; red[3][t] += red[3][t + o];
                }
                __syncthreads();
            }
            if (t == 0) {
                g_M[m] = red[0][0];
                g_C0[m * 3 + 0] = red[1][0];
                g_C0[m * 3 + 1] = red[2][0];
                g_C0[m * 3 + 2] = red[3][0];
            }
        } else {
            int idx = blk - NM;
            int j = idx / 3, c = idx - 3 * j;
            float s = 0.f;
            for (int v = t; v < NVRT; v += 256) s += vs[v * 3 + c] * Jr[v * 21 + j];
            red[0][t] = s; __syncthreads();
            for (int o = 128; o > 0; o >>= 1) {
                if (t < o) red[0][t] += red[0][t + o];
                __syncthreads();
            }
            if (t == 0) g_Jk[j * 3 + c] = red[0][0];
        }
    } else {
        __shared__ float As[32][33];
        __shared__ float Bs[32][33];
        int b2 = blk - (NM + 63);
        int ks = b2 / 143;
        int rem = b2 - ks * 143;
        int m0 = (rem % 11) * 32;
        int fc0 = (rem / 11) * 32;
        int kbase = ks * KSEG, kend = kbase + KSEG;
        int tx = t & 15, ty = t >> 4;
        float acc[2][2] = {};
        for (int k0 = kbase; k0 < kend; k0 += 32) {
#pragma unroll
            for (int r = 0; r < 4; r++) {
                int e = t + 256 * r; int kk = e & 31, fl = e >> 5;
                int fc = fc0 + fl, k = k0 + kk;
                As[fl][kk] = (fc < NFC && k < kend) ? g_Pp[fc * PPLD + k] : 0.f;
            }
#pragma unroll
            for (int r = 0; r < 4; r++) {
                int e = t + 256 * r; int kk = e & 31, ml = e >> 5;
                int m = m0 + ml, k = k0 + kk;
                Bs[ml][kk] = (m < NM && k < kend) ? g_W2T[m * PPLD + k] : 0.f;
            }
            __syncthreads();
#pragma unroll
            for (int kk = 0; kk < 32; kk++) {
                float a0 = As[ty][kk], a1 = As[ty + 16][kk];
                float b0 = Bs[tx][kk], b1 = Bs[tx + 16][kk];
                acc[0][0] += a0 * b0; acc[0][1] += a0 * b1;
                acc[1][0] += a1 * b0; acc[1][1] += a1 * b1;
            }
            __syncthreads();
        }
#pragma unroll
        for (int i = 0; i < 2; i++) {
            int fc = fc0 + ty + 16 * i;
            if (fc >= NFC) continue;
            int f = fc / 3, c = fc - 3 * f;
#pragma unroll
            for (int jj = 0; jj < 2; jj++) {
                int m = m0 + tx + 16 * jj;
                if (m < NM) g_Dp[(ks * NF + f) * NNP + m * 3 + c] = acc[i][jj];
            }
        }
    }
}

// ================ stage C: combine split-K partials ================
__global__ void k_red() {
    int idx = blockIdx.x * 256 + threadIdx.x;   // grid covers NF*NNP exactly
    const int S = NF * NNP;
    float s = 0.f;
#pragma unroll
    for (int k = 0; k < KSPLIT; k++) s += g_Dp[k * S + idx];
    g_D[idx] = s;
}

// ================ fused: pose features + chain + GEMM + epilogue ================
// 512 threads, 28 batches (14 pairs) per tile, grid 293 (= 1.98 waves on 148 SMs).
// Thread: tn = t & 255 (active < 252) -> n = 4*tn..4*tn+3; h = t >> 8 -> pairs 7h..7h+6.
// smem float layout:
//   Ps  [0 .. 28224)      28 x 1008  (aliased early: ths [0..1260), pfp [1264..5584))
//   Asm [28224 .. 33600)  28 x 192
//   Ms  [33600 .. 33936)
//   Ts  [33936 .. 34032)
//   Jks [34032 .. 34080)
// pfp: per f, 128 B: [half h][slot 0..6] u64 pairs (slot 7 unused pad).
#define SMEM_BYTES (34080 * 4)

__device__ __forceinline__ void gstep(const float4& dc, unsigned sp, u64 (&acc)[4][7]) {
    u64 d0 = pk2(dc.x, dc.x), d1 = pk2(dc.y, dc.y),
        d2 = pk2(dc.z, dc.z), d3 = pk2(dc.w, dc.w);
#pragma unroll
    for (int q = 0; q < 3; q++) {
        u64 p0, p1;
        asm("ld.shared.v2.u64 {%0, %1}, [%2];"
            : "=l"(p0), "=l"(p1) : "r"(sp + q * 16));
        acc[0][2 * q]     = fma2(d0, p0, acc[0][2 * q]);
        acc[1][2 * q]     = fma2(d1, p0, acc[1][2 * q]);
        acc[2][2 * q]     = fma2(d2, p0, acc[2][2 * q]);
        acc[3][2 * q]     = fma2(d3, p0, acc[3][2 * q]);
        acc[0][2 * q + 1] = fma2(d0, p1, acc[0][2 * q + 1]);
        acc[1][2 * q + 1] = fma2(d1, p1, acc[1][2 * q + 1]);
        acc[2][2 * q + 1] = fma2(d2, p1, acc[2][2 * q + 1]);
        acc[3][2 * q + 1] = fma2(d3, p1, acc[3][2 * q + 1]);
    }
    {
        u64 p6;
        asm("ld.shared.b64 %0, [%1];" : "=l"(p6) : "r"(sp + 48));
        acc[0][6] = fma2(d0, p6, acc[0][6]);
        acc[1][6] = fma2(d1, p6, acc[1][6]);
        acc[2][6] = fma2(d2, p6, acc[2][6]);
        acc[3][6] = fma2(d3, p6, acc[3][6]);
    }
}

__global__ __launch_bounds__(512, 1)
void k_fused(const float* __restrict__ theta, const float* __restrict__ dq,
             const float* __restrict__ iq, const float* __restrict__ tr,
             float* __restrict__ out) {
    extern __shared__ float sm[];
    float* Ps  = sm;
    float* Asm = sm + 28224;
    float* Ms  = sm + 33600;
    float* Ts  = sm + 33936;
    float* Jks = sm + 34032;
    float* ths = sm;                 // alias (dead before Ps writes)
    u64*  pfp  = (u64*)(sm + 1264);  // alias (dead before Ps writes); 16B aligned
    float* pff = sm + 1264;          // float view of pfp

    int t = threadIdx.x;
    int b0 = blockIdx.x * BT;
    int nb = BATCH - b0; if (nb > BT) nb = BT;   // 28, or 16 for last tile
    int tn = t & 255, h = t >> 8;

    // ---- stage inputs (guarded by nb) ----
    for (int i = t; i < nb * 45; i += 512) ths[i] = theta[b0 * 45 + i];
    if (t >= 416 && t < 464) { int i = t - 416; Jks[i] = g_Jk[i]; }
    for (int i = t; i < NM; i += 512) Ms[i] = g_M[i];
    if (t < nb * 3) Ts[t] = tr[b0 * 3 + t];
    __syncthreads();

    // ---- pose features: nb*15 threads, one per (batch, rot) ----
    if (t < nb * 15) {
        int bl = t / 15, i = t - bl * 15;
        const float* th = ths + bl * 45 + 3 * i;
        float tx = th[0], ty = th[1], tz = th[2];
        float ax = tx + 1e-8f, ay = ty + 1e-8f, az = tz + 1e-8f;
        float angle = sqrtf(ax * ax + ay * ay + az * az);
        float inv = 1.0f / angle;
        float nx = tx * inv, ny = ty * inv, nz = tz * inv;
        float sh, ch;
        sincosf(0.5f * angle, &sh, &ch);
        float qw = ch, qx = sh * nx, qy = sh * ny, qz = sh * nz;
        float qn = rsqrtf(qw * qw + qx * qx + qy * qy + qz * qz);
        qw *= qn; qx *= qn; qy *= qn; qz *= qn;
        float w2 = qw * qw, x2 = qx * qx, y2 = qy * qy, z2 = qz * qz;
        float wx = qw * qx, wy = qw * qy, wz = qw * qz;
        float xy = qx * qy, xz = qx * qz, yz = qy * qz;
        float o[9];
        o[0] = w2 + x2 - y2 - z2 - 1.0f;
        o[1] = 2.f * (xy - wz);
        o[2] = 2.f * (wy + xz);
        o[3] = 2.f * (wz + xy);
        o[4] = w2 - x2 + y2 - z2 - 1.0f;
        o[5] = 2.f * (yz - wx);
        o[6] = 2.f * (xz - wy);
        o[7] = 2.f * (wx + yz);
        o[8] = w2 - x2 - y2 + z2 - 1.0f;
        int pr = bl >> 1, lo = bl & 1;
        int half = (pr >= 7) ? 1 : 0;
        int slot = pr - 7 * half;
#pragma unroll
        for (int e = 0; e < 9; e++)
            pff[(9 * i + e) * 32 + half * 16 + slot * 2 + lo] = o[e];
    }
    __syncthreads();

    // ---- kinematic chain: nb*3 threads, one per (batch, row k) ----
    if (t < nb * 3) {
        int bl = t / 3, k = t - bl * 3;
        int b = b0 + bl;
        float w1 = dq[b * 4 + 0], x1 = dq[b * 4 + 1], y1 = dq[b * 4 + 2], z1 = dq[b * 4 + 3];
        float w2q = iq[0], x2q = iq[1], y2q = iq[2], z2q = iq[3];
        float qw = w1 * w2q - x1 * x2q - y1 * y2q - z1 * z2q;
        float qx = w1 * x2q + x1 * w2q + y1 * z2q - z1 * y2q;
        float qy = w1 * y2q - x1 * z2q + y1 * w2q + z1 * x2q;
        float qz = w1 * z2q + x1 * y2q - y1 * x2q + z1 * w2q;
        float qn = rsqrtf(qw * qw + qx * qx + qy * qy + qz * qz);
        qw *= qn; qx *= qn; qy *= qn; qz *= qn;
        float W2_ = qw * qw, X2 = qx * qx, Y2 = qy * qy, Z2 = qz * qz;
        float WX = qw * qx, WY = qw * qy, WZ = qw * qz;
        float XY = qx * qy, XZ = qx * qz, YZ = qy * qz;
        float R[9];
        R[0] = W2_ + X2 - Y2 - Z2; R[1] = 2.f * (XY - WZ);    R[2] = 2.f * (WY + XZ);
        R[3] = 2.f * (WZ + XY);    R[4] = W2_ - X2 + Y2 - Z2; R[5] = 2.f * (YZ - WX);
        R[6] = 2.f * (XZ - WY);    R[7] = 2.f * (WX + YZ);    R[8] = W2_ - X2 - Y2 + Z2;

        float rr0 = R[3 * k + 0], rr1 = R[3 * k + 1], rr2 = R[3 * k + 2];
        float rt = Jks[k];
        float* Ao = Asm + bl * 192;
        {
            float jx = Jks[0], jy = Jks[1], jz = Jks[2];
            Ao[k * 3 + 0] = rr0; Ao[k * 3 + 1] = rr1; Ao[k * 3 + 2] = rr2;
            Ao[9 + k] = rt - (rr0 * jx + rr1 * jy + rr2 * jz);
        }
        int pr = bl >> 1, lo = bl & 1;
        int half = (pr >= 7) ? 1 : 0;
        int slot = pr - 7 * half;
#pragma unroll
        for (int chn = 0; chn < 5; chn++) {
            float cr0 = rr0, cr1 = rr1, cr2 = rr2, ct = rt;
#pragma unroll
            for (int s = 0; s < 3; s++) {
                int i = chn * 3 + 1 + s;
                int p = (s == 0) ? 0 : (i - 1);
                float Ri[9];
#pragma unroll
                for (int e = 0; e < 9; e++)
                    Ri[e] = pff[(9 * (i - 1) + e) * 32 + half * 16 + slot * 2 + lo]
                          + ((e == 0 || e == 4 || e == 8) ? 1.0f : 0.0f);
                float rx = Jks[3 * i + 0] - Jks[3 * p + 0];
                float ry = Jks[3 * i + 1] - Jks[3 * p + 1];
                float rz = Jks[3 * i + 2] - Jks[3 * p + 2];
                float n0 = cr0 * Ri[0] + cr1 * Ri[3] + cr2 * Ri[6];
                float n1 = cr0 * Ri[1] + cr1 * Ri[4] + cr2 * Ri[7];
                float n2 = cr0 * Ri[2] + cr1 * Ri[5] + cr2 * Ri[8];
                float nt = cr0 * rx + cr1 * ry + cr2 * rz + ct;
                float jx = Jks[3 * i + 0], jy = Jks[3 * i + 1], jz = Jks[3 * i + 2];
                float* Aoi = Ao + i * 12;
                Aoi[k * 3 + 0] = n0; Aoi[k * 3 + 1] = n1; Aoi[k * 3 + 2] = n2;
                Aoi[9 + k] = nt - (n0 * jx + n1 * jy + n2 * jz);
                cr0 = n0; cr1 = n1; cr2 = n2; ct = nt;
            }
        }
    }

    // ---- main GEMM: n = 4tn..4tn+3, 7 pairs, depth-4 D prefetch ----
    u64 acc[4][7];
    {
        float4 cc = *(const float4*)&g_C0[4 * tn];
        u64 c0 = pk2(cc.x, cc.x), c1 = pk2(cc.y, cc.y),
            c2 = pk2(cc.z, cc.z), c3 = pk2(cc.w, cc.w);
#pragma unroll
        for (int p = 0; p < 7; p++) {
            acc[0][p] = c0; acc[1][p] = c1; acc[2][p] = c2; acc[3][p] = c3;
        }
    }
    const float4* dl = (const float4*)(g_D + 4 * tn);   // row r at dl[r*256]
    float4 dbuf[4];
    dbuf[0] = dl[0]; dbuf[1] = dl[256]; dbuf[2] = dl[512]; dbuf[3] = dl[768];
    dl += 1024;                                          // points at row 4

    unsigned sp;
    {
        unsigned pbase = (unsigned)__cvta_generic_to_shared(pfp);
        sp = pbase + h * 64;                             // per-f stride 128 B
    }

    for (int f0 = 0; f0 < 128; f0 += 4) {
#pragma unroll
        for (int u = 0; u < 4; u++) {
            float4 dc = dbuf[u];
            dbuf[u] = dl[u * 256];                       // row f0+u+4 (<= 131, valid)
            gstep(dc, sp + u * 128, acc);
        }
        dl += 1024;
        sp += 512;
    }
    // dbuf holds rows 128..131; dl points at row 132
#pragma unroll
    for (int u = 0; u < 3; u++) {
        float4 dc = dbuf[u];
        dbuf[u] = dl[u * 256];                           // rows 132..134
        gstep(dc, sp + u * 128, acc);                    // f = 128..130
    }
    gstep(dbuf[3], sp + 3 * 128, acc);                   // f = 131
#pragma unroll
    for (int u = 0; u < 3; u++) {
        gstep(dbuf[u], sp + (4 + u) * 128, acc);         // f = 132..134
    }
    __syncthreads();   // pfp/ths now dead

    // ---- spill P to smem ----
    if (tn < 252) {
#pragma unroll
        for (int p = 0; p < 7; p++) {
            int bg = 2 * (7 * h + p);
#pragma unroll
            for (int k = 0; k < 4; k++) {
                float x0, x1;
                upk2(acc[k][p], x0, x1);
                Ps[bg * NN + 4 * tn + k] = x0;
                Ps[(bg + 1) * NN + 4 * tn + k] = x1;
            }
        }
    }
    __syncthreads();

    // ---- epilogue: joints = A ∘ P + M*t + trans ----
    for (int idx = t; idx < nb * 63; idx += 512) {
        int bl = idx / 63;
        int r = idx - bl * 63;
        int jo = r / 3;
        int k = r - jo * 3;
        const float* Ab = Asm + bl * 192;
        const float* Pb = Ps + bl * NN;
        float s = Ts[bl * 3 + k];
#pragma unroll
        for (int j = 0; j < 16; j++) {
            int rb = j * 12 + k * 3;
            int pb = (jo * 16 + j) * 3;
            s += Ab[rb] * Pb[pb] + Ab[rb + 1] * Pb[pb + 1] + Ab[rb + 2] * Pb[pb + 2]
               + Ms[jo * 16 + j] * Ab[j * 12 + 9 + k];
        }
        out[(b0 + bl) * 63 + jo * 3 + k] = s;
    }
}

// ---------------- launcher ----------------
extern "C" void kernel_launch(void* const* d_in, const int* in_sizes, int n_in,
                              void* d_out, int out_size) {
    const float* theta = (const float*)d_in[0];
    const float* dq    = (const float*)d_in[1];
    const float* us    = (const float*)d_in[2];
    const float* iq    = (const float*)d_in[3];
    const float* tr    = (const float*)d_in[4];
    const float* vt    = (const float*)d_in[5];
    const float* sd    = (const float*)d_in[6];
    const float* Jr    = (const float*)d_in[7];
    const float* pd    = (const float*)d_in[8];
    const float* wg    = (const float*)d_in[9];
    float* out = (float*)d_out;

    cudaFuncSetAttribute(k_fused, cudaFuncAttributeMaxDynamicSharedMemorySize, SMEM_BYTES);

    k_A<<<25 + PP_BLKS, 256>>>(us, sd, vt, Jr, wg, pd);
    k_B<<<NM + 63 + 143 * KSPLIT, 256>>>(Jr);
    k_red<<<(NF * NNP) / 256, 256>>>();
    k_fused<<<NTILE, 512, SMEM_BYTES>>>(theta, dq, iq, tr, out);
}

// round 10
// speedup vs baseline: 1.6406x; 1.0065x over previous
#include <cuda_runtime.h>
#include <math.h>

#define BATCH 8192
#define NVRT  778
#define NJO   21
#define NF    135
#define NM    336      /* 21*16 */
#define NN    1008     /* NM*3  */
#define NNP   1024
#define NFC   405      /* NF*3  */
#define PPLD  784
#define KSPLIT 8
#define KSEG  98       /* PPLD / KSPLIT */

#define BT    28       /* batches per fused tile */
#define NTILE 293      /* ceil(8192/28) */

// ---------------- scratch (__device__ globals; zero-init; padding never written) ----
__device__ float g_vsh[NVRT * 3];
__device__ float g_Jk[64];
__device__ float g_W2T[NM * PPLD];       // [m][v], rows padded to 784 (tail stays 0)
__device__ float g_Pp[NFC * PPLD];       // [fc][v], tail stays 0
__device__ float g_M[NM];
__device__ float g_C0[NNP];              // [1008..1024) stays 0
__device__ float g_Dp[KSPLIT * NF * NNP];// split-K partials (padding never written -> 0)
__device__ float g_D[NF * NNP];          // combined (padding written 0 by reduce)

// ---------------- f32x2 helpers ----------------
typedef unsigned long long u64;
__device__ __forceinline__ u64 pk2(float x, float y) {
    u64 r; asm("mov.b64 %0, {%1, %2};" : "=l"(r) : "f"(x), "f"(y)); return r;
}
__device__ __forceinline__ void upk2(u64 v, float& x, float& y) {
    asm("mov.b64 {%0, %1}, %2;" : "=f"(x), "=f"(y) : "l"(v));
}
__device__ __forceinline__ u64 fma2(u64 a, u64 b, u64 c) {
    u64 d; asm("fma.rn.f32x2 %0, %1, %2, %3;" : "=l"(d) : "l"(a), "l"(b), "l"(c)); return d;
}

// ================ stage A: vsh + W2T (25 blocks)  ||  Pp transpose (1231 blocks) ========
#define PP_BLKS ((NFC * NVRT + 255) / 256)
__global__ void k_A(const float* __restrict__ us, const float* __restrict__ sd,
                    const float* __restrict__ vt, const float* __restrict__ Jr,
                    const float* __restrict__ wg, const float* __restrict__ pd) {
    int t = threadIdx.x;
    if (blockIdx.x < 25) {
        __shared__ float jrs[32 * 21];
        __shared__ float wgs[32 * 17];
        int v0 = blockIdx.x * 32;
        int nv = NVRT - v0; if (nv > 32) nv = 32;
        for (int i = t; i < nv * 21; i += 256) jrs[i] = Jr[v0 * 21 + i];
        for (int i = t; i < nv * 16; i += 256) {
            int vl = i >> 4, j = i & 15;
            wgs[vl * 17 + j] = wg[(v0 + vl) * 16 + j];
        }
        for (int i = t; i < nv * 3; i += 256) {
            int g = v0 * 3 + i;
            float s = vt[g];
#pragma unroll
            for (int q = 0; q < 10; q++) s += us[q] * sd[q * 2334 + g];
            g_vsh[g] = s;
        }
        __syncthreads();
        for (int i = t; i < NM * 32; i += 256) {
            int vl = i & 31, m = i >> 5;
            int v = v0 + vl;
            if (v < NVRT)
                g_W2T[m * PPLD + v] = jrs[vl * 21 + (m >> 4)] * wgs[vl * 17 + (m & 15)];
        }
    } else {
        int idx = (blockIdx.x - 25) * 256 + t;
        if (idx < NFC * NVRT) {
            int fc = idx / NVRT, v = idx - fc * NVRT;
            int f = fc / 3, c = fc - 3 * f;
            g_Pp[fc * PPLD + v] = pd[f * 2334 + 3 * v + c];
        }
    }
}

// ================ stage B: Jk/M/C0 (399 blocks)  ||  D split-K partials ====
__global__ void k_B(const float* __restrict__ Jr) {
    int t = threadIdx.x;
    int blk = blockIdx.x;
    if (blk < NM + 63) {
        __shared__ float vs[NVRT * 3];
        __shared__ float red[4][256];
        for (int i = t; i < NVRT * 3; i += 256) vs[i] = g_vsh[i];
        __syncthreads();
        if (blk < NM) {
            int m = blk;
            float sm = 0.f, s0 = 0.f, s1 = 0.f, s2 = 0.f;
            for (int v = t; v < NVRT; v += 256) {
                float w = g_W2T[m * PPLD + v];
                sm += w;
                s0 += w * vs[v * 3 + 0];
                s1 += w * vs[v * 3 + 1];
                s2 += w * vs[v * 3 + 2];
            }
            red[0][t] = sm; red[1][t] = s0; red[2][t] = s1; red[3][t] = s2;
            __syncthreads();
            for (int o = 128; o > 0; o >>= 1) {
                if (t < o) {
                    red[0][t] += red[0][t + o]; red[1][t] += red[1][t + o];
                    red[2][t] += red[2][t + o]; red[3][t] += red[3][t + o];
                }
                __syncthreads();
            }
            if (t == 0) {
                g_M[m] = red[0][0];
                g_C0[m * 3 + 0] = red[1][0];
                g_C0[m * 3 + 1] = red[2][0];
                g_C0[m * 3 + 2] = red[3][0];
            }
        } else {
            int idx = blk - NM;
            int j = idx / 3, c = idx - 3 * j;
            float s = 0.f;
            for (int v = t; v < NVRT; v += 256) s += vs[v * 3 + c] * Jr[v * 21 + j];
            red[0][t] = s; __syncthreads();
            for (int o = 128; o > 0; o >>= 1) {
                if (t < o) red[0][t] += red[0][t + o];
                __syncthreads();
            }
            if (t == 0) g_Jk[j * 3 + c] = red[0][0];
        }
    } else {
        __shared__ float As[32][33];
        __shared__ float Bs[32][33];
        int b2 = blk - (NM + 63);
        int ks = b2 / 143;
        int rem = b2 - ks * 143;
        int m0 = (rem % 11) * 32;
        int fc0 = (rem / 11) * 32;
        int kbase = ks * KSEG, kend = kbase + KSEG;
        int tx = t & 15, ty = t >> 4;
        float acc[2][2] = {};
        for (int k0 = kbase; k0 < kend; k0 += 32) {
#pragma unroll
            for (int r = 0; r < 4; r++) {
                int e = t + 256 * r; int kk = e & 31, fl = e >> 5;
                int fc = fc0 + fl, k = k0 + kk;
                As[fl][kk] = (fc < NFC && k < kend) ? g_Pp[fc * PPLD + k] : 0.f;
            }
#pragma unroll
            for (int r = 0; r < 4; r++) {
                int e = t + 256 * r; int kk = e & 31, ml = e >> 5;
                int m = m0 + ml, k = k0 + kk;
                Bs[ml][kk] = (m < NM && k < kend) ? g_W2T[m * PPLD + k] : 0.f;
            }
            __syncthreads();
#pragma unroll
            for (int kk = 0; kk < 32; kk++) {
                float a0 = As[ty][kk], a1 = As[ty + 16][kk];
                float b0 = Bs[tx][kk], b1 = Bs[tx + 16][kk];
                acc[0][0] += a0 * b0; acc[0][1] += a0 * b1;
                acc[1][0] += a1 * b0; acc[1][1] += a1 * b1;
            }
            __syncthreads();
        }
#pragma unroll
        for (int i = 0; i < 2; i++) {
            int fc = fc0 + ty + 16 * i;
            if (fc >= NFC) continue;
            int f = fc / 3, c = fc - 3 * f;
#pragma unroll
            for (int jj = 0; jj < 2; jj++) {
                int m = m0 + tx + 16 * jj;
                if (m < NM) g_Dp[(ks * NF + f) * NNP + m * 3 + c] = acc[i][jj];
            }
        }
    }
}

// ================ stage C: combine split-K partials ================
__global__ void k_red() {
    int idx = blockIdx.x * 256 + threadIdx.x;   // grid covers NF*NNP exactly
    const int S = NF * NNP;
    float s = 0.f;
#pragma unroll
    for (int k = 0; k < KSPLIT; k++) s += g_Dp[k * S + idx];
    g_D[idx] = s;
}

// ================ fused: pose features + chain + GEMM + epilogue ================
// 256 threads, 28 batches (14 pairs) per tile, grid 293.
// Thread t owns n = 4t..4t+3 (active t < 252 for spill) and ALL 14 batch-pairs.
// acc = 4 x 14 u64 = 112 regs/thread; 256 threads -> ~49k regs/SM.
// smem float layout:
//   Ps  [0 .. 28224)      28 x 1008  (aliased early: ths [0..1260), pfp [1264..5584))
//   Asm [28224 .. 33600)  28 x 192
//   Ms  [33600 .. 33936)
//   Ts  [33936 .. 34032)
//   Jks [34032 .. 34080)
// pfp: per f, 128 B = 16 u64 slots; slot pr (0..13) = batches (2pr, 2pr+1) packed.
#define SMEM_BYTES (34080 * 4)

__device__ __forceinline__ void gstep(const float4& dc, unsigned sp, u64 (&acc)[4][14]) {
    u64 d0 = pk2(dc.x, dc.x), d1 = pk2(dc.y, dc.y),
        d2 = pk2(dc.z, dc.z), d3 = pk2(dc.w, dc.w);
#pragma unroll
    for (int q = 0; q < 7; q++) {
        u64 p0, p1;
        asm("ld.shared.v2.u64 {%0, %1}, [%2];"
            : "=l"(p0), "=l"(p1) : "r"(sp + q * 16));
        acc[0][2 * q]     = fma2(d0, p0, acc[0][2 * q]);
        acc[1][2 * q]     = fma2(d1, p0, acc[1][2 * q]);
        acc[2][2 * q]     = fma2(d2, p0, acc[2][2 * q]);
        acc[3][2 * q]     = fma2(d3, p0, acc[3][2 * q]);
        acc[0][2 * q + 1] = fma2(d0, p1, acc[0][2 * q + 1]);
        acc[1][2 * q + 1] = fma2(d1, p1, acc[1][2 * q + 1]);
        acc[2][2 * q + 1] = fma2(d2, p1, acc[2][2 * q + 1]);
        acc[3][2 * q + 1] = fma2(d3, p1, acc[3][2 * q + 1]);
    }
}

__global__ __launch_bounds__(256, 1)
void k_fused(const float* __restrict__ theta, const float* __restrict__ dq,
             const float* __restrict__ iq, const float* __restrict__ tr,
             float* __restrict__ out) {
    extern __shared__ float sm[];
    float* Ps  = sm;
    float* Asm = sm + 28224;
    float* Ms  = sm + 33600;
    float* Ts  = sm + 33936;
    float* Jks = sm + 34032;
    float* ths = sm;                 // alias (dead before Ps writes)
    u64*  pfp  = (u64*)(sm + 1264);  // alias (dead before Ps writes); 16B aligned
    float* pff = sm + 1264;          // float view of pfp

    int t = threadIdx.x;
    int b0 = blockIdx.x * BT;
    int nb = BATCH - b0; if (nb > BT) nb = BT;   // 28, or 16 for last tile

    // ---- stage inputs (guarded by nb) ----
    for (int i = t; i < nb * 45; i += 256) ths[i] = theta[b0 * 45 + i];
    if (t >= 96 && t < 144) { int i = t - 96; Jks[i] = g_Jk[i]; }
    for (int i = t; i < NM; i += 256) Ms[i] = g_M[i];
    if (t < nb * 3) Ts[t] = tr[b0 * 3 + t];
    __syncthreads();

    // ---- pose features: nb*15 items (<=420), loop over 256 threads ----
    for (int it = t; it < nb * 15; it += 256) {
        int bl = it / 15, i = it - bl * 15;
        const float* th = ths + bl * 45 + 3 * i;
        float tx = th[0], ty = th[1], tz = th[2];
        float ax = tx + 1e-8f, ay = ty + 1e-8f, az = tz + 1e-8f;
        float angle = sqrtf(ax * ax + ay * ay + az * az);
        float inv = 1.0f / angle;
        float nx = tx * inv, ny = ty * inv, nz = tz * inv;
        float sh, ch;
        sincosf(0.5f * angle, &sh, &ch);
        float qw = ch, qx = sh * nx, qy = sh * ny, qz = sh * nz;
        float qn = rsqrtf(qw * qw + qx * qx + qy * qy + qz * qz);
        qw *= qn; qx *= qn; qy *= qn; qz *= qn;
        float w2 = qw * qw, x2 = qx * qx, y2 = qy * qy, z2 = qz * qz;
        float wx = qw * qx, wy = qw * qy, wz = qw * qz;
        float xy = qx * qy, xz = qx * qz, yz = qy * qz;
        float o[9];
        o[0] = w2 + x2 - y2 - z2 - 1.0f;
        o[1] = 2.f * (xy - wz);
        o[2] = 2.f * (wy + xz);
        o[3] = 2.f * (wz + xy);
        o[4] = w2 - x2 + y2 - z2 - 1.0f;
        o[5] = 2.f * (yz - wx);
        o[6] = 2.f * (xz - wy);
        o[7] = 2.f * (wx + yz);
        o[8] = w2 - x2 - y2 + z2 - 1.0f;
        int pr = bl >> 1, lo = bl & 1;
#pragma unroll
        for (int e = 0; e < 9; e++)
            pff[(9 * i + e) * 32 + pr * 2 + lo] = o[e];
    }
    __syncthreads();

    // ---- kinematic chain: nb*3 threads (<=84), one per (batch, row k) ----
    if (t < nb * 3) {
        int bl = t / 3, k = t - bl * 3;
        int b = b0 + bl;
        float w1 = dq[b * 4 + 0], x1 = dq[b * 4 + 1], y1 = dq[b * 4 + 2], z1 = dq[b * 4 + 3];
        float w2q = iq[0], x2q = iq[1], y2q = iq[2], z2q = iq[3];
        float qw = w1 * w2q - x1 * x2q - y1 * y2q - z1 * z2q;
        float qx = w1 * x2q + x1 * w2q + y1 * z2q - z1 * y2q;
        float qy = w1 * y2q - x1 * z2q + y1 * w2q + z1 * x2q;
        float qz = w1 * z2q + x1 * y2q - y1 * x2q + z1 * w2q;
        float qn = rsqrtf(qw * qw + qx * qx + qy * qy + qz * qz);
        qw *= qn; qx *= qn; qy *= qn; qz *= qn;
        float W2_ = qw * qw, X2 = qx * qx, Y2 = qy * qy, Z2 = qz * qz;
        float WX = qw * qx, WY = qw * qy, WZ = qw * qz;
        float XY = qx * qy, XZ = qx * qz, YZ = qy * qz;
        float R[9];
        R[0] = W2_ + X2 - Y2 - Z2; R[1] = 2.f * (XY - WZ);    R[2] = 2.f * (WY + XZ);
        R[3] = 2.f * (WZ + XY);    R[4] = W2_ - X2 + Y2 - Z2; R[5] = 2.f * (YZ - WX);
        R[6] = 2.f * (XZ - WY);    R[7] = 2.f * (WX + YZ);    R[8] = W2_ - X2 - Y2 + Z2;

        float rr0 = R[3 * k + 0], rr1 = R[3 * k + 1], rr2 = R[3 * k + 2];
        float rt = Jks[k];
        float* Ao = Asm + bl * 192;
        {
            float jx = Jks[0], jy = Jks[1], jz = Jks[2];
            Ao[k * 3 + 0] = rr0; Ao[k * 3 + 1] = rr1; Ao[k * 3 + 2] = rr2;
            Ao[9 + k] = rt - (rr0 * jx + rr1 * jy + rr2 * jz);
        }
        int pr = bl >> 1, lo = bl & 1;
#pragma unroll
        for (int chn = 0; chn < 5; chn++) {
            float cr0 = rr0, cr1 = rr1, cr2 = rr2, ct = rt;
#pragma unroll
            for (int s = 0; s < 3; s++) {
                int i = chn * 3 + 1 + s;
                int p = (s == 0) ? 0 : (i - 1);
                float Ri[9];
#pragma unroll
                for (int e = 0; e < 9; e++)
                    Ri[e] = pff[(9 * (i - 1) + e) * 32 + pr * 2 + lo]
                          + ((e == 0 || e == 4 || e == 8) ? 1.0f : 0.0f);
                float rx = Jks[3 * i + 0] - Jks[3 * p + 0];
                float ry = Jks[3 * i + 1] - Jks[3 * p + 1];
                float rz = Jks[3 * i + 2] - Jks[3 * p + 2];
                float n0 = cr0 * Ri[0] + cr1 * Ri[3] + cr2 * Ri[6];
                float n1 = cr0 * Ri[1] + cr1 * Ri[4] + cr2 * Ri[7];
                float n2 = cr0 * Ri[2] + cr1 * Ri[5] + cr2 * Ri[8];
                float nt = cr0 * rx + cr1 * ry + cr2 * rz + ct;
                float jx = Jks[3 * i + 0], jy = Jks[3 * i + 1], jz = Jks[3 * i + 2];
                float* Aoi = Ao + i * 12;
                Aoi[k * 3 + 0] = n0; Aoi[k * 3 + 1] = n1; Aoi[k * 3 + 2] = n2;
                Aoi[9 + k] = nt - (n0 * jx + n1 * jy + n2 * jz);
                cr0 = n0; cr1 = n1; cr2 = n2; ct = nt;
            }
        }
    }

    // ---- main GEMM: n = 4t..4t+3, 14 pairs, depth-4 D prefetch ----
    u64 acc[4][14];
    {
        float4 cc = *(const float4*)&g_C0[4 * t];
        u64 c0 = pk2(cc.x, cc.x), c1 = pk2(cc.y, cc.y),
            c2 = pk2(cc.z, cc.z), c3 = pk2(cc.w, cc.w);
#pragma unroll
        for (int p = 0; p < 14; p++) {
            acc[0][p] = c0; acc[1][p] = c1; acc[2][p] = c2; acc[3][p] = c3;
        }
    }
    const float4* dl = (const float4*)(g_D + 4 * t);    // row r at dl[r*256]
    float4 dbuf[4];
    dbuf[0] = dl[0]; dbuf[1] = dl[256]; dbuf[2] = dl[512]; dbuf[3] = dl[768];
    dl += 1024;                                          // points at row 4

    unsigned sp = (unsigned)__cvta_generic_to_shared(pfp);  // per-f stride 128 B

    for (int f0 = 0; f0 < 128; f0 += 4) {
#pragma unroll
        for (int u = 0; u < 4; u++) {
            float4 dc = dbuf[u];
            dbuf[u] = dl[u * 256];                       // row f0+u+4 (<= 131, valid)
            gstep(dc, sp + u * 128, acc);
        }
        dl += 1024;
        sp += 512;
    }
    // dbuf holds rows 128..131; dl points at row 132
#pragma unroll
    for (int u = 0; u < 3; u++) {
        float4 dc = dbuf[u];
        dbuf[u] = dl[u * 256];                           // rows 132..134
        gstep(dc, sp + u * 128, acc);                    // f = 128..130
    }
    gstep(dbuf[3], sp + 3 * 128, acc);                   // f = 131
#pragma unroll
    for (int u = 0; u < 3; u++) {
        gstep(dbuf[u], sp + (4 + u) * 128, acc);         // f = 132..134
    }
    __syncthreads();   // pfp/ths now dead

    // ---- spill P to smem ----
    if (t < 252) {
#pragma unroll
        for (int p = 0; p < 14; p++) {
            int bg = 2 * p;
#pragma unroll
            for (int k = 0; k < 4; k++) {
                float x0, x1;
                upk2(acc[k][p], x0, x1);
                Ps[bg * NN + 4 * t + k] = x0;
                Ps[(bg + 1) * NN + 4 * t + k] = x1;
            }
        }
    }
    __syncthreads();

    // ---- epilogue: joints = A ∘ P + M*t + trans ----
    for (int idx = t; idx < nb * 63; idx += 256) {
        int bl = idx / 63;
        int r = idx - bl * 63;
        int jo = r / 3;
        int k = r - jo * 3;
        const float* Ab = Asm + bl * 192;
        const float* Pb = Ps + bl * NN;
        float s = Ts[bl * 3 + k];
#pragma unroll
        for (int j = 0; j < 16; j++) {
            int rb = j * 12 + k * 3;
            int pb = (jo * 16 + j) * 3;
            s += Ab[rb] * Pb[pb] + Ab[rb + 1] * Pb[pb + 1] + Ab[rb + 2] * Pb[pb + 2]
               + Ms[jo * 16 + j] * Ab[j * 12 + 9 + k];
        }
        out[(b0 + bl) * 63 + jo * 3 + k] = s;
    }
}

// ---------------- launcher ----------------
extern "C" void kernel_launch(void* const* d_in, const int* in_sizes, int n_in,
                              void* d_out, int out_size) {
    const float* theta = (const float*)d_in[0];
    const float* dq    = (const float*)d_in[1];
    const float* us    = (const float*)d_in[2];
    const float* iq    = (const float*)d_in[3];
    const float* tr    = (const float*)d_in[4];
    const float* vt    = (const float*)d_in[5];
    const float* sd    = (const float*)d_in[6];
    const float* Jr    = (const float*)d_in[7];
    const float* pd    = (const float*)d_in[8];
    const float* wg    = (const float*)d_in[9];
    float* out = (float*)d_out;

    cudaFuncSetAttribute(k_fused, cudaFuncAttributeMaxDynamicSharedMemorySize, SMEM_BYTES);

    k_A<<<25 + PP_BLKS, 256>>>(us, sd, vt, Jr, wg, pd);
    k_B<<<NM + 63 + 143 * KSPLIT, 256>>>(Jr);
    k_red<<<(NF * NNP) / 256, 256>>>();
    k_fused<<<NTILE, 256, SMEM_BYTES>>>(theta, dq, iq, tr, out);
}

// round 11
// speedup vs baseline: 1.6429x; 1.0014x over previous
#include <cuda_runtime.h>
#include <math.h>

#define BATCH 8192
#define NVRT  778
#define NJO   21
#define NF    135
#define NM    336      /* 21*16 */
#define NN    1008     /* NM*3  */
#define NNP   1024
#define NFC   405      /* NF*3  */
#define PPLD  784
#define KSPLIT 8
#define KSEG  98       /* PPLD / KSPLIT */

#define BT    28       /* batches per fused tile */
#define NTILE 293      /* ceil(8192/28) */

// ---------------- scratch (__device__ globals; zero-init; padding never written) ----
__device__ float g_vsh[NVRT * 3];
__device__ float g_Jk[64];
__device__ float g_W2T[NM * PPLD];       // [m][v], rows padded to 784 (tail stays 0)
__device__ float g_Pp[NFC * PPLD];       // [fc][v], tail stays 0
__device__ float g_M[NM];
__device__ float g_C0[NNP];              // [1008..1024) stays 0
__device__ float g_Dp[KSPLIT * NF * NNP];// split-K partials (padding never written -> 0)
__device__ float g_D[NF * NNP];          // combined (padding written 0 by reduce)

// ---------------- f32x2 helpers ----------------
typedef unsigned long long u64;
__device__ __forceinline__ u64 pk2(float x, float y) {
    u64 r; asm("mov.b64 %0, {%1, %2};" : "=l"(r) : "f"(x), "f"(y)); return r;
}
__device__ __forceinline__ void upk2(u64 v, float& x, float& y) {
    asm("mov.b64 {%0, %1}, %2;" : "=f"(x), "=f"(y) : "l"(v));
}
__device__ __forceinline__ u64 fma2(u64 a, u64 b, u64 c) {
    u64 d; asm("fma.rn.f32x2 %0, %1, %2, %3;" : "=l"(d) : "l"(a), "l"(b), "l"(c)); return d;
}

// ================ stage A: vsh + W2T (25 blocks)  ||  Pp transpose (1231 blocks) ========
#define PP_BLKS ((NFC * NVRT + 255) / 256)
__global__ void k_A(const float* __restrict__ us, const float* __restrict__ sd,
                    const float* __restrict__ vt, const float* __restrict__ Jr,
                    const float* __restrict__ wg, const float* __restrict__ pd) {
    int t = threadIdx.x;
    if (blockIdx.x < 25) {
        __shared__ float jrs[32 * 21];
        __shared__ float wgs[32 * 17];
        int v0 = blockIdx.x * 32;
        int nv = NVRT - v0; if (nv > 32) nv = 32;
        for (int i = t; i < nv * 21; i += 256) jrs[i] = Jr[v0 * 21 + i];
        for (int i = t; i < nv * 16; i += 256) {
            int vl = i >> 4, j = i & 15;
            wgs[vl * 17 + j] = wg[(v0 + vl) * 16 + j];
        }
        for (int i = t; i < nv * 3; i += 256) {
            int g = v0 * 3 + i;
            float s = vt[g];
#pragma unroll
            for (int q = 0; q < 10; q++) s += us[q] * sd[q * 2334 + g];
            g_vsh[g] = s;
        }
        __syncthreads();
        for (int i = t; i < NM * 32; i += 256) {
            int vl = i & 31, m = i >> 5;
            int v = v0 + vl;
            if (v < NVRT)
                g_W2T[m * PPLD + v] = jrs[vl * 21 + (m >> 4)] * wgs[vl * 17 + (m & 15)];
        }
    } else {
        int idx = (blockIdx.x - 25) * 256 + t;
        if (idx < NFC * NVRT) {
            int fc = idx / NVRT, v = idx - fc * NVRT;
            int f = fc / 3, c = fc - 3 * f;
            g_Pp[fc * PPLD + v] = pd[f * 2334 + 3 * v + c];
        }
    }
}

// ================ stage B: Jk/M/C0 (399 blocks)  ||  D split-K partials ====
__global__ void k_B(const float* __restrict__ Jr) {
    int t = threadIdx.x;
    int blk = blockIdx.x;
    if (blk < NM + 63) {
        __shared__ float vs[NVRT * 3];
        __shared__ float red[4][256];
        for (int i = t; i < NVRT * 3; i += 256) vs[i] = g_vsh[i];
        __syncthreads();
        if (blk < NM) {
            int m = blk;
            float sm = 0.f, s0 = 0.f, s1 = 0.f, s2 = 0.f;
            for (int v = t; v < NVRT; v += 256) {
                float w = g_W2T[m * PPLD + v];
                sm += w;
                s0 += w * vs[v * 3 + 0];
                s1 += w * vs[v * 3 + 1];
                s2 += w * vs[v * 3 + 2];
            }
            red[0][t] = sm; red[1][t] = s0; red[2][t] = s1; red[3][t] = s2;
            __syncthreads();
            for (int o = 128; o > 0; o >>= 1) {
                if (t < o) {
                    red[0][t] += red[0][t + o]; red[1][t] += red[1][t + o];
                    red[2][t] += red[2][t + o]; red[3][t] += red[3][t + o];
                }
                __syncthreads();
            }
            if (t == 0) {
                g_M[m] = red[0][0];
                g_C0[m * 3 + 0] = red[1][0];
                g_C0[m * 3 + 1] = red[2][0];
                g_C0[m * 3 + 2] = red[3][0];
            }
        } else {
            int idx = blk - NM;
            int j = idx / 3, c = idx - 3 * j;
            float s = 0.f;
            for (int v = t; v < NVRT; v += 256) s += vs[v * 3 + c] * Jr[v * 21 + j];
            red[0][t] = s; __syncthreads();
            for (int o = 128; o > 0; o >>= 1) {
                if (t < o) red[0][t] += red[0][t + o];
                __syncthreads();
            }
            if (t == 0) g_Jk[j * 3 + c] = red[0][0];
        }
    } else {
        __shared__ float As[32][33];
        __shared__ float Bs[32][33];
        int b2 = blk - (NM + 63);
        int ks = b2 / 143;
        int rem = b2 - ks * 143;
        int m0 = (rem % 11) * 32;
        int fc0 = (rem / 11) * 32;
        int kbase = ks * KSEG, kend = kbase + KSEG;
        int tx = t & 15, ty = t >> 4;
        float acc[2][2] = {};
        for (int k0 = kbase; k0 < kend; k0 += 32) {
#pragma unroll
            for (int r = 0; r < 4; r++) {
                int e = t + 256 * r; int kk = e & 31, fl = e >> 5;
                int fc = fc0 + fl, k = k0 + kk;
                As[fl][kk] = (fc < NFC && k < kend) ? g_Pp[fc * PPLD + k] : 0.f;
            }
#pragma unroll
            for (int r = 0; r < 4; r++) {
                int e = t + 256 * r; int kk = e & 31, ml = e >> 5;
                int m = m0 + ml, k = k0 + kk;
                Bs[ml][kk] = (m < NM && k < kend) ? g_W2T[m * PPLD + k] : 0.f;
            }
            __syncthreads();
#pragma unroll
            for (int kk = 0; kk < 32; kk++) {
                float a0 = As[ty][kk], a1 = As[ty + 16][kk];
                float b0 = Bs[tx][kk], b1 = Bs[tx + 16][kk];
                acc[0][0] += a0 * b0; acc[0][1] += a0 * b1;
                acc[1][0] += a1 * b0; acc[1][1] += a1 * b1;
            }
            __syncthreads();
        }
#pragma unroll
        for (int i = 0; i < 2; i++) {
            int fc = fc0 + ty + 16 * i;
            if (fc >= NFC) continue;
            int f = fc / 3, c = fc - 3 * f;
#pragma unroll
            for (int jj = 0; jj < 2; jj++) {
                int m = m0 + tx + 16 * jj;
                if (m < NM) g_Dp[(ks * NF + f) * NNP + m * 3 + c] = acc[i][jj];
            }
        }
    }
}

// ================ stage C: combine split-K partials ================
__global__ void k_red() {
    int idx = blockIdx.x * 256 + threadIdx.x;   // grid covers NF*NNP exactly
    const int S = NF * NNP;
    float s = 0.f;
#pragma unroll
    for (int k = 0; k < KSPLIT; k++) s += g_Dp[k * S + idx];
    g_D[idx] = s;
}

// ================ fused: pose features + chain + GEMM + epilogue ================
// 256 threads, 28 batches (14 pairs) per tile, grid 293.
// Thread t owns n = 4t..4t+3 (active t < 252 for spill) and ALL 14 batch-pairs.
// GEMM inner loop: depth-4 D prefetch (LDG) + 1-row pf double buffer (LDS) so the
// LDS->fma RAW (29 cyc) is covered by a full row of 56 fma2.
// smem float layout:
//   Ps  [0 .. 28224)      28 x 1008  (aliased early: ths [0..1260), pfp [1264..5584))
//   Asm [28224 .. 33600)  28 x 192
//   Ms  [33600 .. 33936)
//   Ts  [33936 .. 34032)
//   Jks [34032 .. 34080)
// pfp: per f, 128 B = 16 u64 slots; slot pr (0..13) = batches (2pr, 2pr+1) packed.
#define SMEM_BYTES (34080 * 4)

__device__ __forceinline__ void ldsrow(u64 (&p)[14], unsigned sp) {
#pragma unroll
    for (int q = 0; q < 7; q++)
        asm("ld.shared.v2.u64 {%0, %1}, [%2];"
            : "=l"(p[2 * q]), "=l"(p[2 * q + 1]) : "r"(sp + q * 16));
}

__device__ __forceinline__ void fmarow(const float4& dc, const u64 (&p)[14],
                                       u64 (&acc)[4][14]) {
    u64 d0 = pk2(dc.x, dc.x), d1 = pk2(dc.y, dc.y),
        d2 = pk2(dc.z, dc.z), d3 = pk2(dc.w, dc.w);
#pragma unroll
    for (int j = 0; j < 14; j++) {
        acc[0][j] = fma2(d0, p[j], acc[0][j]);
        acc[1][j] = fma2(d1, p[j], acc[1][j]);
        acc[2][j] = fma2(d2, p[j], acc[2][j]);
        acc[3][j] = fma2(d3, p[j], acc[3][j]);
    }
}

__global__ __launch_bounds__(256, 1)
void k_fused(const float* __restrict__ theta, const float* __restrict__ dq,
             const float* __restrict__ iq, const float* __restrict__ tr,
             float* __restrict__ out) {
    extern __shared__ float sm[];
    float* Ps  = sm;
    float* Asm = sm + 28224;
    float* Ms  = sm + 33600;
    float* Ts  = sm + 33936;
    float* Jks = sm + 34032;
    float* ths = sm;                 // alias (dead before Ps writes)
    u64*  pfp  = (u64*)(sm + 1264);  // alias (dead before Ps writes); 16B aligned
    float* pff = sm + 1264;          // float view of pfp

    int t = threadIdx.x;
    int b0 = blockIdx.x * BT;
    int nb = BATCH - b0; if (nb > BT) nb = BT;   // 28, or 16 for last tile

    // ---- stage inputs (guarded by nb) ----
    for (int i = t; i < nb * 45; i += 256) ths[i] = theta[b0 * 45 + i];
    if (t >= 96 && t < 144) { int i = t - 96; Jks[i] = g_Jk[i]; }
    for (int i = t; i < NM; i += 256) Ms[i] = g_M[i];
    if (t < nb * 3) Ts[t] = tr[b0 * 3 + t];
    __syncthreads();

    // ---- pose features: nb*15 items (<=420), loop over 256 threads ----
    for (int it = t; it < nb * 15; it += 256) {
        int bl = it / 15, i = it - bl * 15;
        const float* th = ths + bl * 45 + 3 * i;
        float tx = th[0], ty = th[1], tz = th[2];
        float ax = tx + 1e-8f, ay = ty + 1e-8f, az = tz + 1e-8f;
        float angle = sqrtf(ax * ax + ay * ay + az * az);
        float inv = 1.0f / angle;
        float nx = tx * inv, ny = ty * inv, nz = tz * inv;
        float sh, ch;
        sincosf(0.5f * angle, &sh, &ch);
        float qw = ch, qx = sh * nx, qy = sh * ny, qz = sh * nz;
        float qn = rsqrtf(qw * qw + qx * qx + qy * qy + qz * qz);
        qw *= qn; qx *= qn; qy *= qn; qz *= qn;
        float w2 = qw * qw, x2 = qx * qx, y2 = qy * qy, z2 = qz * qz;
        float wx = qw * qx, wy = qw * qy, wz = qw * qz;
        float xy = qx * qy, xz = qx * qz, yz = qy * qz;
        float o[9];
        o[0] = w2 + x2 - y2 - z2 - 1.0f;
        o[1] = 2.f * (xy - wz);
        o[2] = 2.f * (wy + xz);
        o[3] = 2.f * (wz + xy);
        o[4] = w2 - x2 + y2 - z2 - 1.0f;
        o[5] = 2.f * (yz - wx);
        o[6] = 2.f * (xz - wy);
        o[7] = 2.f * (wx + yz);
        o[8] = w2 - x2 - y2 + z2 - 1.0f;
        int pr = bl >> 1, lo = bl & 1;
#pragma unroll
        for (int e = 0; e < 9; e++)
            pff[(9 * i + e) * 32 + pr * 2 + lo] = o[e];
    }
    __syncthreads();

    // ---- kinematic chain: nb*3 threads (<=84), one per (batch, row k) ----
    if (t < nb * 3) {
        int bl = t / 3, k = t - bl * 3;
        int b = b0 + bl;
        float w1 = dq[b * 4 + 0], x1 = dq[b * 4 + 1], y1 = dq[b * 4 + 2], z1 = dq[b * 4 + 3];
        float w2q = iq[0], x2q = iq[1], y2q = iq[2], z2q = iq[3];
        float qw = w1 * w2q - x1 * x2q - y1 * y2q - z1 * z2q;
        float qx = w1 * x2q + x1 * w2q + y1 * z2q - z1 * y2q;
        float qy = w1 * y2q - x1 * z2q + y1 * w2q + z1 * x2q;
        float qz = w1 * z2q + x1 * y2q - y1 * x2q + z1 * w2q;
        float qn = rsqrtf(qw * qw + qx * qx + qy * qy + qz * qz);
        qw *= qn; qx *= qn; qy *= qn; qz *= qn;
        float W2_ = qw * qw, X2 = qx * qx, Y2 = qy * qy, Z2 = qz * qz;
        float WX = qw * qx, WY = qw * qy, WZ = qw * qz;
        float XY = qx * qy, XZ = qx * qz, YZ = qy * qz;
        float R[9];
        R[0] = W2_ + X2 - Y2 - Z2; R[1] = 2.f * (XY - WZ);    R[2] = 2.f * (WY + XZ);
        R[3] = 2.f * (WZ + XY);    R[4] = W2_ - X2 + Y2 - Z2; R[5] = 2.f * (YZ - WX);
        R[6] = 2.f * (XZ - WY);    R[7] = 2.f * (WX + YZ);    R[8] = W2_ - X2 - Y2 + Z2;

        float rr0 = R[3 * k + 0], rr1 = R[3 * k + 1], rr2 = R[3 * k + 2];
        float rt = Jks[k];
        float* Ao = Asm + bl * 192;
        {
            float jx = Jks[0], jy = Jks[1], jz = Jks[2];
            Ao[k * 3 + 0] = rr0; Ao[k * 3 + 1] = rr1; Ao[k * 3 + 2] = rr2;
            Ao[9 + k] = rt - (rr0 * jx + rr1 * jy + rr2 * jz);
        }
        int pr = bl >> 1, lo = bl & 1;
#pragma unroll
        for (int chn = 0; chn < 5; chn++) {
            float cr0 = rr0, cr1 = rr1, cr2 = rr2, ct = rt;
#pragma unroll
            for (int s = 0; s < 3; s++) {
                int i = chn * 3 + 1 + s;
                int p = (s == 0) ? 0 : (i - 1);
                float Ri[9];
#pragma unroll
                for (int e = 0; e < 9; e++)
                    Ri[e] = pff[(9 * (i - 1) + e) * 32 + pr * 2 + lo]
                          + ((e == 0 || e == 4 || e == 8) ? 1.0f : 0.0f);
                float rx = Jks[3 * i + 0] - Jks[3 * p + 0];
                float ry = Jks[3 * i + 1] - Jks[3 * p + 1];
                float rz = Jks[3 * i + 2] - Jks[3 * p + 2];
                float n0 = cr0 * Ri[0] + cr1 * Ri[3] + cr2 * Ri[6];
                float n1 = cr0 * Ri[1] + cr1 * Ri[4] + cr2 * Ri[7];
                float n2 = cr0 * Ri[2] + cr1 * Ri[5] + cr2 * Ri[8];
                float nt = cr0 * rx + cr1 * ry + cr2 * rz + ct;
                float jx = Jks[3 * i + 0], jy = Jks[3 * i + 1], jz = Jks[3 * i + 2];
                float* Aoi = Ao + i * 12;
                Aoi[k * 3 + 0] = n0; Aoi[k * 3 + 1] = n1; Aoi[k * 3 + 2] = n2;
                Aoi[9 + k] = nt - (n0 * jx + n1 * jy + n2 * jz);
                cr0 = n0; cr1 = n1; cr2 = n2; ct = nt;
            }
        }
    }

    // ---- main GEMM: n = 4t..4t+3, 14 pairs, depth-4 D prefetch + pf double buffer ----
    u64 acc[4][14];
    {
        float4 cc = *(const float4*)&g_C0[4 * t];
        u64 c0 = pk2(cc.x, cc.x), c1 = pk2(cc.y, cc.y),
            c2 = pk2(cc.z, cc.z), c3 = pk2(cc.w, cc.w);
#pragma unroll
        for (int p = 0; p < 14; p++) {
            acc[0][p] = c0; acc[1][p] = c1; acc[2][p] = c2; acc[3][p] = c3;
        }
    }
    const float4* dl = (const float4*)(g_D + 4 * t);    // row r at dl[r*256]
    float4 dbuf[4];
    dbuf[0] = dl[0]; dbuf[1] = dl[256]; dbuf[2] = dl[512]; dbuf[3] = dl[768];
    dl += 1024;                                          // points at row 4

    unsigned sp = (unsigned)__cvta_generic_to_shared(pfp);  // per-f stride 128 B

    u64 pA[14], pB[14];
    ldsrow(pA, sp);                                      // pf row 0

    for (int f0 = 0; f0 < 128; f0 += 4) {
        float4 dc;
        dc = dbuf[0]; dbuf[0] = dl[0];   ldsrow(pB, sp + 128); fmarow(dc, pA, acc);
        dc = dbuf[1]; dbuf[1] = dl[256]; ldsrow(pA, sp + 256); fmarow(dc, pB, acc);
        dc = dbuf[2]; dbuf[2] = dl[512]; ldsrow(pB, sp + 384); fmarow(dc, pA, acc);
        dc = dbuf[3]; dbuf[3] = dl[768]; ldsrow(pA, sp + 512); fmarow(dc, pB, acc);
        dl += 1024;
        sp += 512;
    }
    // state: pA = pf row 128, dbuf = D rows 128..131, dl -> row 132, sp -> row 128
    {
        float4 dc;
        dc = dbuf[0]; dbuf[0] = dl[0];   ldsrow(pB, sp + 128); fmarow(dc, pA, acc); // f=128
        dc = dbuf[1]; dbuf[1] = dl[256]; ldsrow(pA, sp + 256); fmarow(dc, pB, acc); // f=129
        dc = dbuf[2]; dbuf[2] = dl[512]; ldsrow(pB, sp + 384); fmarow(dc, pA, acc); // f=130
        dc = dbuf[3];                    ldsrow(pA, sp + 512); fmarow(dc, pB, acc); // f=131
        dc = dbuf[0];                    ldsrow(pB, sp + 640); fmarow(dc, pA, acc); // f=132
        dc = dbuf[1];                    ldsrow(pA, sp + 768); fmarow(dc, pB, acc); // f=133
        dc = dbuf[2];                                          fmarow(dc, pA, acc); // f=134
    }
    __syncthreads();   // pfp/ths now dead

    // ---- spill P to smem ----
    if (t < 252) {
#pragma unroll
        for (int p = 0; p < 14; p++) {
            int bg = 2 * p;
#pragma unroll
            for (int k = 0; k < 4; k++) {
                float x0, x1;
                upk2(acc[k][p], x0, x1);
                Ps[bg * NN + 4 * t + k] = x0;
                Ps[(bg + 1) * NN + 4 * t + k] = x1;
            }
        }
    }
    __syncthreads();

    // ---- epilogue: joints = A ∘ P + M*t + trans ----
    for (int idx = t; idx < nb * 63; idx += 256) {
        int bl = idx / 63;
        int r = idx - bl * 63;
        int jo = r / 3;
        int k = r - jo * 3;
        const float* Ab = Asm + bl * 192;
        const float* Pb = Ps + bl * NN;
        float s = Ts[bl * 3 + k];
#pragma unroll
        for (int j = 0; j < 16; j++) {
            int rb = j * 12 + k * 3;
            int pb = (jo * 16 + j) * 3;
            s += Ab[rb] * Pb[pb] + Ab[rb + 1] * Pb[pb + 1] + Ab[rb + 2] * Pb[pb + 2]
               + Ms[jo * 16 + j] * Ab[j * 12 + 9 + k];
        }
        out[(b0 + bl) * 63 + jo * 3 + k] = s;
    }
}

// ---------------- launcher ----------------
extern "C" void kernel_launch(void* const* d_in, const int* in_sizes, int n_in,
                              void* d_out, int out_size) {
    const float* theta = (const float*)d_in[0];
    const float* dq    = (const float*)d_in[1];
    const float* us    = (const float*)d_in[2];
    const float* iq    = (const float*)d_in[3];
    const float* tr    = (const float*)d_in[4];
    const float* vt    = (const float*)d_in[5];
    const float* sd    = (const float*)d_in[6];
    const float* Jr    = (const float*)d_in[7];
    const float* pd    = (const float*)d_in[8];
    const float* wg    = (const float*)d_in[9];
    float* out = (float*)d_out;

    cudaFuncSetAttribute(k_fused, cudaFuncAttributeMaxDynamicSharedMemorySize, SMEM_BYTES);

    k_A<<<25 + PP_BLKS, 256>>>(us, sd, vt, Jr, wg, pd);
    k_B<<<NM + 63 + 143 * KSPLIT, 256>>>(Jr);
    k_red<<<(NF * NNP) / 256, 256>>>();
    k_fused<<<NTILE, 256, SMEM_BYTES>>>(theta, dq, iq, tr, out);
}